// round 1
// baseline (speedup 1.0000x reference)
#include <cuda_runtime.h>
#include <math.h>

#define TOK  4096          // B*32*32 tokens
#define CH   768
#define NSEQ 1024          // tokens per image
#define BHD  48            // B * heads
#define HD   64
#define MLPD 3072
#define QKVD 2304

// ---------------- scratch (device globals; no allocations) ----------------
__device__ float g_h   [TOK*CH];
__device__ float g_ln  [TOK*CH];
__device__ float g_col [TOK*CH];
__device__ float g_wt  [CH*CH];
__device__ float g_qkv [TOK*QKVD];
__device__ float g_q   [BHD*NSEQ*HD];
__device__ float g_k   [BHD*NSEQ*HD];
__device__ float g_v   [BHD*NSEQ*HD];
__device__ float g_relh[BHD*NSEQ*32];
__device__ float g_relw[BHD*NSEQ*32];
__device__ float g_S   [(size_t)BHD*NSEQ*NSEQ];   // 201 MB
__device__ float g_ao  [TOK*CH];
__device__ float g_mlp [TOK*MLPD];

// ---------------- small helpers ----------------
__global__ void im2col_k(const float* __restrict__ x, float* __restrict__ out) {
    int idx = blockIdx.x * 256 + threadIdx.x;           // < TOK*CH
    int token = idx / 768, kk = idx % 768;
    int ci = kk >> 8, r = kk & 255, py = r >> 4, px = r & 15;
    int b = token >> 10, g = token & 1023, gy = g >> 5, gx = g & 31;
    out[idx] = x[(((size_t)(b*3 + ci) * 512) + gy*16 + py) * 512 + gx*16 + px];
}

__global__ void transpose_k(const float* __restrict__ w, float* __restrict__ wt) {
    int idx = blockIdx.x * 256 + threadIdx.x;           // < 768*768
    wt[(idx % 768) * 768 + (idx / 768)] = w[idx];
}

__global__ void addpos_k(float* __restrict__ h, const float* __restrict__ pos) {
    int idx = blockIdx.x * 256 + threadIdx.x;           // < TOK*CH
    h[idx] += pos[idx % (NSEQ*CH)];
}

__global__ void qkv_split_k(const float* __restrict__ qkv,
                            float* __restrict__ q, float* __restrict__ k, float* __restrict__ v) {
    int idx = blockIdx.x * 256 + threadIdx.x;           // < TOK*QKVD
    int token = idx / QKVD, col = idx % QKVD;
    int which = col / 768, rem = col % 768;
    int head = rem >> 6, d = rem & 63;
    int b = token >> 10, n = token & 1023;
    float val = qkv[idx];
    size_t dst = ((size_t)(b*12 + head) * NSEQ + n) * HD + d;
    if (which == 0)      q[dst] = val;
    else if (which == 1) k[dst] = val;
    else                 v[dst] = val;
}

// decomposed relative position: relh[bh,q,ky] = sum_d q[bh,q,d]*Rh[qy-ky+31,d]
__global__ void rel_k(const float* __restrict__ q,
                      const float* __restrict__ rph, const float* __restrict__ rpw,
                      float* __restrict__ relh, float* __restrict__ relw) {
    int gw   = blockIdx.x * 8 + (threadIdx.x >> 5);     // (bh, qi) pair, < BHD*NSEQ
    int lane = threadIdx.x & 31;
    int bh = gw >> 10, qi = gw & 1023;
    int qy = qi >> 5, qx = qi & 31;
    const float* qp = q + ((size_t)bh * NSEQ + qi) * HD;
    const float* rh = rph + (qy - lane + 31) * HD;
    const float* rw = rpw + (qx - lane + 31) * HD;
    float sh = 0.f, sw = 0.f;
#pragma unroll
    for (int d = 0; d < HD; d++) { float qd = qp[d]; sh += qd * rh[d]; sw += qd * rw[d]; }
    relh[(size_t)gw * 32 + lane] = sh;
    relw[(size_t)gw * 32 + lane] = sw;
}

__global__ void layernorm_k(const float* __restrict__ x, const float* __restrict__ w,
                            const float* __restrict__ b, float* __restrict__ y) {
    int row = blockIdx.x;
    const float* xr = x + (size_t)row * CH;
    int t = threadIdx.x;                                 // 256 threads, 3 elems each
    float v0 = xr[t], v1 = xr[t+256], v2 = xr[t+512];
    __shared__ float red[256];
    red[t] = v0 + v1 + v2;
    __syncthreads();
    for (int o = 128; o > 0; o >>= 1) { if (t < o) red[t] += red[t+o]; __syncthreads(); }
    float mean = red[0] * (1.f/768.f);
    __syncthreads();
    float d0 = v0-mean, d1 = v1-mean, d2 = v2-mean;
    red[t] = d0*d0 + d1*d1 + d2*d2;
    __syncthreads();
    for (int o = 128; o > 0; o >>= 1) { if (t < o) red[t] += red[t+o]; __syncthreads(); }
    float rstd = rsqrtf(red[0] * (1.f/768.f) + 1e-5f);
    float* yr = y + (size_t)row * CH;
    yr[t]     = d0 * rstd * w[t]     + b[t];
    yr[t+256] = d1 * rstd * w[t+256] + b[t+256];
    yr[t+512] = d2 * rstd * w[t+512] + b[t+512];
}

__global__ void softmax_k(float* __restrict__ S) {
    float* r = S + (size_t)blockIdx.x * NSEQ;
    int t = threadIdx.x;                                 // 256 threads, 4 elems
    float v0 = r[t], v1 = r[t+256], v2 = r[t+512], v3 = r[t+768];
    __shared__ float red[256];
    red[t] = fmaxf(fmaxf(v0, v1), fmaxf(v2, v3));
    __syncthreads();
    for (int o = 128; o > 0; o >>= 1) { if (t < o) red[t] = fmaxf(red[t], red[t+o]); __syncthreads(); }
    float m = red[0];
    __syncthreads();
    v0 = __expf(v0 - m); v1 = __expf(v1 - m); v2 = __expf(v2 - m); v3 = __expf(v3 - m);
    red[t] = v0 + v1 + v2 + v3;
    __syncthreads();
    for (int o = 128; o > 0; o >>= 1) { if (t < o) red[t] += red[t+o]; __syncthreads(); }
    float inv = 1.f / red[0];
    r[t] = v0*inv; r[t+256] = v1*inv; r[t+512] = v2*inv; r[t+768] = v3*inv;
}

// ---------------- generic tiled fp32 GEMM: C = A(MxK) @ B(KxN) + bias, epilogue ----
// EPI: 0 = bias, 1 = bias+exact GELU, 2 = bias + residual add (res[row*N+col])
template <int EPI>
__global__ void sgemm_nn(const float* __restrict__ A, const float* __restrict__ Bm,
                         const float* __restrict__ bias, const float* __restrict__ res,
                         float* __restrict__ C, int M, int N, int K) {
    __shared__ float As[16][65];
    __shared__ float Bs[16][65];
    int tx = threadIdx.x;
    int brow = blockIdx.y * 64, bcol = blockIdx.x * 64;
    int tr = tx >> 4, tc = tx & 15;
    float acc[4][4] = {};
    for (int k0 = 0; k0 < K; k0 += 16) {
        for (int t = tx; t < 1024; t += 256) {
            int m = t >> 4, kk = t & 15;
            As[kk][m] = A[(size_t)(brow + m) * K + k0 + kk];
        }
        for (int t = tx; t < 1024; t += 256) {
            int kk = t >> 6, n = t & 63;
            Bs[kk][n] = Bm[(size_t)(k0 + kk) * N + bcol + n];
        }
        __syncthreads();
#pragma unroll
        for (int kk = 0; kk < 16; kk++) {
            float a[4], bb[4];
#pragma unroll
            for (int i = 0; i < 4; i++) a[i]  = As[kk][tr*4 + i];
#pragma unroll
            for (int j = 0; j < 4; j++) bb[j] = Bs[kk][tc*4 + j];
#pragma unroll
            for (int i = 0; i < 4; i++)
#pragma unroll
                for (int j = 0; j < 4; j++) acc[i][j] += a[i] * bb[j];
        }
        __syncthreads();
    }
#pragma unroll
    for (int i = 0; i < 4; i++) {
        int row = brow + tr*4 + i;
#pragma unroll
        for (int j = 0; j < 4; j++) {
            int col = bcol + tc*4 + j;
            float v = acc[i][j] + bias[col];
            if (EPI == 1) v = 0.5f * v * (1.f + erff(v * 0.70710678118f));
            if (EPI == 2) v += res[(size_t)row * N + col];
            C[(size_t)row * N + col] = v;
        }
    }
}

// ---------------- attention scores: S = scale*q @ k^T + rel  (48 batches, K=64, NT) ---
__global__ void attn_scores_k(const float* __restrict__ q, const float* __restrict__ k,
                              const float* __restrict__ relh, const float* __restrict__ relw,
                              float* __restrict__ S) {
    int bh = blockIdx.z;
    const float* A = q + (size_t)bh * NSEQ * HD;
    const float* B = k + (size_t)bh * NSEQ * HD;
    __shared__ float As[16][65];
    __shared__ float Bs[16][65];
    int tx = threadIdx.x;
    int brow = blockIdx.y * 64, bcol = blockIdx.x * 64;
    int tr = tx >> 4, tc = tx & 15;
    float acc[4][4] = {};
    for (int k0 = 0; k0 < HD; k0 += 16) {
        for (int t = tx; t < 1024; t += 256) {
            int m = t >> 4, kk = t & 15;
            As[kk][m] = A[(size_t)(brow + m) * HD + k0 + kk] * 0.125f;
            Bs[kk][m] = B[(size_t)(bcol + m) * HD + k0 + kk];
        }
        __syncthreads();
#pragma unroll
        for (int kk = 0; kk < 16; kk++) {
            float a[4], bb[4];
#pragma unroll
            for (int i = 0; i < 4; i++) a[i]  = As[kk][tr*4 + i];
#pragma unroll
            for (int j = 0; j < 4; j++) bb[j] = Bs[kk][tc*4 + j];
#pragma unroll
            for (int i = 0; i < 4; i++)
#pragma unroll
                for (int j = 0; j < 4; j++) acc[i][j] += a[i] * bb[j];
        }
        __syncthreads();
    }
#pragma unroll
    for (int i = 0; i < 4; i++) {
        int row = brow + tr*4 + i;
        const float* rh = relh + ((size_t)bh * NSEQ + row) * 32;
        const float* rw = relw + ((size_t)bh * NSEQ + row) * 32;
#pragma unroll
        for (int j = 0; j < 4; j++) {
            int col = bcol + tc*4 + j;
            S[((size_t)bh * NSEQ + row) * NSEQ + col] =
                acc[i][j] + rh[col >> 5] + rw[col & 31];
        }
    }
}

// ---------------- attn @ v (48 batches, 1024x64x1024, NN) with head-scatter -----------
__global__ void attn_av_k(const float* __restrict__ S, const float* __restrict__ v,
                          float* __restrict__ out) {
    int bh = blockIdx.z;
    const float* A = S + (size_t)bh * NSEQ * NSEQ;
    const float* B = v + (size_t)bh * NSEQ * HD;
    __shared__ float As[16][65];
    __shared__ float Bs[16][65];
    int tx = threadIdx.x;
    int brow = blockIdx.y * 64;
    int tr = tx >> 4, tc = tx & 15;
    float acc[4][4] = {};
    for (int k0 = 0; k0 < NSEQ; k0 += 16) {
        for (int t = tx; t < 1024; t += 256) {
            int m = t >> 4, kk = t & 15;
            As[kk][m] = A[(size_t)(brow + m) * NSEQ + k0 + kk];
        }
        for (int t = tx; t < 1024; t += 256) {
            int kk = t >> 6, n = t & 63;
            Bs[kk][n] = B[(size_t)(k0 + kk) * HD + n];
        }
        __syncthreads();
#pragma unroll
        for (int kk = 0; kk < 16; kk++) {
            float a[4], bb[4];
#pragma unroll
            for (int i = 0; i < 4; i++) a[i]  = As[kk][tr*4 + i];
#pragma unroll
            for (int j = 0; j < 4; j++) bb[j] = Bs[kk][tc*4 + j];
#pragma unroll
            for (int i = 0; i < 4; i++)
#pragma unroll
                for (int j = 0; j < 4; j++) acc[i][j] += a[i] * bb[j];
        }
        __syncthreads();
    }
    int b = bh / 12, head = bh % 12;
#pragma unroll
    for (int i = 0; i < 4; i++) {
        int row = brow + tr*4 + i;
#pragma unroll
        for (int j = 0; j < 4; j++) {
            int col = tc*4 + j;
            out[((size_t)(b * NSEQ + row)) * CH + head * 64 + col] = acc[i][j];
        }
    }
}

// ---------------- orchestration ----------------
extern "C" void kernel_launch(void* const* d_in, const int* in_sizes, int n_in,
                              void* d_out, int out_size) {
    const float* x         = (const float*)d_in[0];
    const float* conv_w    = (const float*)d_in[1];
    const float* conv_b    = (const float*)d_in[2];
    const float* pos_embed = (const float*)d_in[3];
    const float* ln1_w     = (const float*)d_in[4];
    const float* ln1_b     = (const float*)d_in[5];
    const float* qkv_w     = (const float*)d_in[6];
    const float* qkv_b     = (const float*)d_in[7];
    const float* proj_w    = (const float*)d_in[8];
    const float* proj_b    = (const float*)d_in[9];
    const float* rel_pos_h = (const float*)d_in[10];
    const float* rel_pos_w = (const float*)d_in[11];
    const float* ln2_w     = (const float*)d_in[12];
    const float* ln2_b     = (const float*)d_in[13];
    const float* fc1_w     = (const float*)d_in[14];
    const float* fc1_b     = (const float*)d_in[15];
    const float* fc2_w     = (const float*)d_in[16];
    const float* fc2_b     = (const float*)d_in[17];

    float *h, *ln, *colb, *wt, *qkvb, *q, *k, *v, *relh, *relw, *S, *ao, *mlp;
    cudaGetSymbolAddress((void**)&h,    g_h);
    cudaGetSymbolAddress((void**)&ln,   g_ln);
    cudaGetSymbolAddress((void**)&colb, g_col);
    cudaGetSymbolAddress((void**)&wt,   g_wt);
    cudaGetSymbolAddress((void**)&qkvb, g_qkv);
    cudaGetSymbolAddress((void**)&q,    g_q);
    cudaGetSymbolAddress((void**)&k,    g_k);
    cudaGetSymbolAddress((void**)&v,    g_v);
    cudaGetSymbolAddress((void**)&relh, g_relh);
    cudaGetSymbolAddress((void**)&relw, g_relw);
    cudaGetSymbolAddress((void**)&S,    g_S);
    cudaGetSymbolAddress((void**)&ao,   g_ao);
    cudaGetSymbolAddress((void**)&mlp,  g_mlp);

    // patch embed = im2col + GEMM with transposed conv weights, then + pos_embed
    im2col_k   <<<TOK*CH/256, 256>>>(x, colb);
    transpose_k<<<CH*CH/256, 256>>>(conv_w, wt);
    sgemm_nn<0><<<dim3(CH/64, TOK/64), 256>>>(colb, wt, conv_b, nullptr, h, TOK, CH, CH);
    addpos_k   <<<TOK*CH/256, 256>>>(h, pos_embed);

    for (int i = 0; i < 4; i++) {
        layernorm_k<<<TOK, 256>>>(h, ln1_w + i*CH, ln1_b + i*CH, ln);
        sgemm_nn<0><<<dim3(QKVD/64, TOK/64), 256>>>(ln, qkv_w + (size_t)i*CH*QKVD,
                                                    qkv_b + i*QKVD, nullptr, qkvb,
                                                    TOK, QKVD, CH);
        qkv_split_k<<<TOK*QKVD/256, 256>>>(qkvb, q, k, v);
        rel_k<<<BHD*NSEQ/8, 256>>>(q, rel_pos_h + i*63*HD, rel_pos_w + i*63*HD, relh, relw);
        attn_scores_k<<<dim3(16, 16, BHD), 256>>>(q, k, relh, relw, S);
        softmax_k<<<BHD*NSEQ, 256>>>(S);
        attn_av_k<<<dim3(1, 16, BHD), 256>>>(S, v, ao);
        sgemm_nn<2><<<dim3(CH/64, TOK/64), 256>>>(ao, proj_w + (size_t)i*CH*CH,
                                                  proj_b + i*CH, h, h, TOK, CH, CH);
        layernorm_k<<<TOK, 256>>>(h, ln2_w + i*CH, ln2_b + i*CH, ln);
        sgemm_nn<1><<<dim3(MLPD/64, TOK/64), 256>>>(ln, fc1_w + (size_t)i*CH*MLPD,
                                                    fc1_b + i*MLPD, nullptr, mlp,
                                                    TOK, MLPD, CH);
        float* dst = (i == 3) ? (float*)d_out : h;
        sgemm_nn<2><<<dim3(CH/64, TOK/64), 256>>>(mlp, fc2_w + (size_t)i*MLPD*CH,
                                                  fc2_b + i*CH, h, dst,
                                                  TOK, CH, MLPD);
    }
}

// round 2
// speedup vs baseline: 2.0698x; 2.0698x over previous
#include <cuda_runtime.h>
#include <math.h>
#include <stdint.h>

#define TOK  4096
#define CH   768
#define NSEQ 1024
#define BHD  48
#define HD   64
#define MLPD 3072
#define QKVD 2304

// ---------------- scratch (device globals; no allocations) ----------------
__device__ float g_h   [TOK*CH];
__device__ float g_ln  [TOK*CH];
__device__ float g_col [TOK*CH];
__device__ float g_wt  [CH*CH];
__device__ float g_q   [BHD*NSEQ*HD];
__device__ float g_k   [BHD*NSEQ*HD];
__device__ float g_v   [BHD*NSEQ*HD];
__device__ float g_relh[BHD*NSEQ*32];
__device__ float g_relw[BHD*NSEQ*32];
__device__ float g_S   [(size_t)BHD*NSEQ*NSEQ];
__device__ float g_ao  [TOK*CH];
__device__ float g_mlp [TOK*MLPD];

// ---------------- tf32 helpers ----------------
__device__ __forceinline__ float f2tf32(float x) {
    uint32_t u;
    asm("cvt.rna.tf32.f32 %0, %1;" : "=r"(u) : "f"(x));
    return __uint_as_float(u);
}

__device__ __forceinline__ void mma_tf32(float* c, const uint32_t* a, const uint32_t* b) {
    asm volatile(
        "mma.sync.aligned.m16n8k8.row.col.f32.tf32.tf32.f32 "
        "{%0,%1,%2,%3}, {%4,%5,%6,%7}, {%8,%9}, {%0,%1,%2,%3};\n"
        : "+f"(c[0]), "+f"(c[1]), "+f"(c[2]), "+f"(c[3])
        : "r"(a[0]), "r"(a[1]), "r"(a[2]), "r"(a[3]), "r"(b[0]), "r"(b[1]));
}

// ---------------- small helpers ----------------
__global__ void im2col_k(const float* __restrict__ x, float* __restrict__ out) {
    int idx = blockIdx.x * 256 + threadIdx.x;
    int token = idx / 768, kk = idx % 768;
    int ci = kk >> 8, r = kk & 255, py = r >> 4, px = r & 15;
    int b = token >> 10, g = token & 1023, gy = g >> 5, gx = g & 31;
    out[idx] = x[(((size_t)(b*3 + ci) * 512) + gy*16 + py) * 512 + gx*16 + px];
}

__global__ void transpose_k(const float* __restrict__ w, float* __restrict__ wt) {
    int idx = blockIdx.x * 256 + threadIdx.x;
    wt[(idx % 768) * 768 + (idx / 768)] = w[idx];
}

__global__ void addpos_k(float* __restrict__ h, const float* __restrict__ pos) {
    int idx = blockIdx.x * 256 + threadIdx.x;
    h[idx] += pos[idx % (NSEQ*CH)];
}

__global__ void rel_k(const float* __restrict__ q,
                      const float* __restrict__ rph, const float* __restrict__ rpw,
                      float* __restrict__ relh, float* __restrict__ relw) {
    int gw   = blockIdx.x * 8 + (threadIdx.x >> 5);
    int lane = threadIdx.x & 31;
    int bh = gw >> 10, qi = gw & 1023;
    int qy = qi >> 5, qx = qi & 31;
    const float* qp = q + ((size_t)bh * NSEQ + qi) * HD;
    const float* rh = rph + (qy - lane + 31) * HD;
    const float* rw = rpw + (qx - lane + 31) * HD;
    float sh = 0.f, sw = 0.f;
#pragma unroll
    for (int d = 0; d < HD; d++) { float qd = qp[d]; sh += qd * rh[d]; sw += qd * rw[d]; }
    relh[(size_t)gw * 32 + lane] = sh;
    relw[(size_t)gw * 32 + lane] = sw;
}

__global__ void layernorm_k(const float* __restrict__ x, const float* __restrict__ w,
                            const float* __restrict__ b, float* __restrict__ y) {
    int row = blockIdx.x;
    const float* xr = x + (size_t)row * CH;
    int t = threadIdx.x;
    float v0 = xr[t], v1 = xr[t+256], v2 = xr[t+512];
    __shared__ float red[256];
    red[t] = v0 + v1 + v2;
    __syncthreads();
    for (int o = 128; o > 0; o >>= 1) { if (t < o) red[t] += red[t+o]; __syncthreads(); }
    float mean = red[0] * (1.f/768.f);
    __syncthreads();
    float d0 = v0-mean, d1 = v1-mean, d2 = v2-mean;
    red[t] = d0*d0 + d1*d1 + d2*d2;
    __syncthreads();
    for (int o = 128; o > 0; o >>= 1) { if (t < o) red[t] += red[t+o]; __syncthreads(); }
    float rstd = rsqrtf(red[0] * (1.f/768.f) + 1e-5f);
    float* yr = y + (size_t)row * CH;
    yr[t]     = d0 * rstd * w[t]     + b[t];
    yr[t+256] = d1 * rstd * w[t+256] + b[t+256];
    yr[t+512] = d2 * rstd * w[t+512] + b[t+512];
}

__global__ void softmax_k(float* __restrict__ S) {
    float* r = S + (size_t)blockIdx.x * NSEQ;
    int t = threadIdx.x;
    float v0 = r[t], v1 = r[t+256], v2 = r[t+512], v3 = r[t+768];
    __shared__ float red[256];
    red[t] = fmaxf(fmaxf(v0, v1), fmaxf(v2, v3));
    __syncthreads();
    for (int o = 128; o > 0; o >>= 1) { if (t < o) red[t] = fmaxf(red[t], red[t+o]); __syncthreads(); }
    float m = red[0];
    __syncthreads();
    v0 = __expf(v0 - m); v1 = __expf(v1 - m); v2 = __expf(v2 - m); v3 = __expf(v3 - m);
    red[t] = v0 + v1 + v2 + v3;
    __syncthreads();
    for (int o = 128; o > 0; o >>= 1) { if (t < o) red[t] += red[t+o]; __syncthreads(); }
    float inv = 1.f / red[0];
    r[t] = v0*inv; r[t+256] = v1*inv; r[t+512] = v2*inv; r[t+768] = v3*inv;
}

// ---------------- tensor-core GEMM (NN): C = A(MxK)@B(KxN) + bias, epilogue ---------
// EPI: 0 = bias, 1 = bias+GELU, 2 = bias+residual, 3 = qkv scatter (C=q, k_out, v_out)
template <int EPI>
__global__ void __launch_bounds__(256)
gemm_tc(const float* __restrict__ A, const float* __restrict__ Bm,
        const float* __restrict__ bias, const float* __restrict__ res,
        float* __restrict__ C, float* __restrict__ k_out, float* __restrict__ v_out,
        int M, int N, int K) {
    __shared__ float As[32][136];
    __shared__ float Bs[32][136];
    int tx = threadIdx.x;
    int wid = tx >> 5, lane = tx & 31;
    int warpM = wid & 3, warpN = wid >> 2;
    int g = lane >> 2, tg = lane & 3;
    int brow = blockIdx.y * 128, bcol = blockIdx.x * 128;

    float acc[2][8][4];
#pragma unroll
    for (int i = 0; i < 2; i++)
#pragma unroll
        for (int j = 0; j < 8; j++)
#pragma unroll
            for (int l = 0; l < 4; l++) acc[i][j][l] = 0.f;

    for (int k0 = 0; k0 < K; k0 += 32) {
#pragma unroll
        for (int i = 0; i < 4; i++) {
            int t4 = tx + i * 256;
            int arow = t4 >> 3, ac4 = t4 & 7;
            float4 va = *(const float4*)&A[(size_t)(brow + arow) * K + k0 + ac4*4];
            As[ac4*4+0][arow] = f2tf32(va.x);
            As[ac4*4+1][arow] = f2tf32(va.y);
            As[ac4*4+2][arow] = f2tf32(va.z);
            As[ac4*4+3][arow] = f2tf32(va.w);
            int brk = t4 >> 5, bc4 = t4 & 31;
            float4 vb = *(const float4*)&Bm[(size_t)(k0 + brk) * N + bcol + bc4*4];
            *(float4*)&Bs[brk][bc4*4] =
                make_float4(f2tf32(vb.x), f2tf32(vb.y), f2tf32(vb.z), f2tf32(vb.w));
        }
        __syncthreads();
#pragma unroll
        for (int ks = 0; ks < 4; ks++) {
            int kk = ks * 8;
            uint32_t a[2][4], b[8][2];
#pragma unroll
            for (int mt = 0; mt < 2; mt++) {
                int m0 = warpM*32 + mt*16;
                a[mt][0] = __float_as_uint(As[kk+tg  ][m0+g  ]);
                a[mt][1] = __float_as_uint(As[kk+tg  ][m0+g+8]);
                a[mt][2] = __float_as_uint(As[kk+tg+4][m0+g  ]);
                a[mt][3] = __float_as_uint(As[kk+tg+4][m0+g+8]);
            }
#pragma unroll
            for (int nt = 0; nt < 8; nt++) {
                int n0 = warpN*64 + nt*8;
                b[nt][0] = __float_as_uint(Bs[kk+tg  ][n0+g]);
                b[nt][1] = __float_as_uint(Bs[kk+tg+4][n0+g]);
            }
#pragma unroll
            for (int mt = 0; mt < 2; mt++)
#pragma unroll
                for (int nt = 0; nt < 8; nt++)
                    mma_tf32(acc[mt][nt], a[mt], b[nt]);
        }
        __syncthreads();
    }

#pragma unroll
    for (int mt = 0; mt < 2; mt++) {
#pragma unroll
        for (int nt = 0; nt < 8; nt++) {
            int r0 = brow + warpM*32 + mt*16 + g;
            int c0 = bcol + warpN*64 + nt*8 + tg*2;
#pragma unroll
            for (int e = 0; e < 4; e++) {
                int row = r0 + (e >> 1) * 8;
                int col = c0 + (e & 1);
                float v = acc[mt][nt][e] + bias[col];
                if (EPI == 1) v = 0.5f * v * (1.f + erff(v * 0.70710678118f));
                if (EPI == 2) v += res[(size_t)row * N + col];
                if (EPI == 3) {
                    int which = col / 768, rem = col - which * 768;
                    int head = rem >> 6, d = rem & 63;
                    int b_ = row >> 10, n_ = row & 1023;
                    size_t dst = ((size_t)(b_*12 + head) * NSEQ + n_) * HD + d;
                    if (which == 0)      C[dst]     = v;
                    else if (which == 1) k_out[dst] = v;
                    else                 v_out[dst] = v;
                } else {
                    C[(size_t)row * N + col] = v;
                }
            }
        }
    }
}

// ---------------- scores: S = scale*q @ k^T + rel (batched NT, K=64) -----------------
__global__ void __launch_bounds__(256)
attn_scores_tc(const float* __restrict__ q, const float* __restrict__ kmat,
               const float* __restrict__ relh, const float* __restrict__ relw,
               float* __restrict__ S) {
    int bh = blockIdx.z;
    const float* A = q    + (size_t)bh * NSEQ * HD;
    const float* B = kmat + (size_t)bh * NSEQ * HD;
    __shared__ float As[32][136];
    __shared__ float Bs[32][136];
    int tx = threadIdx.x;
    int wid = tx >> 5, lane = tx & 31;
    int warpM = wid & 3, warpN = wid >> 2;
    int g = lane >> 2, tg = lane & 3;
    int brow = blockIdx.y * 128, bcol = blockIdx.x * 128;

    float acc[2][8][4];
#pragma unroll
    for (int i = 0; i < 2; i++)
#pragma unroll
        for (int j = 0; j < 8; j++)
#pragma unroll
            for (int l = 0; l < 4; l++) acc[i][j][l] = 0.f;

    for (int k0 = 0; k0 < HD; k0 += 32) {
#pragma unroll
        for (int i = 0; i < 4; i++) {
            int t4 = tx + i * 256;
            int arow = t4 >> 3, ac4 = t4 & 7;
            float4 va = *(const float4*)&A[(size_t)(brow + arow) * HD + k0 + ac4*4];
            As[ac4*4+0][arow] = f2tf32(va.x * 0.125f);
            As[ac4*4+1][arow] = f2tf32(va.y * 0.125f);
            As[ac4*4+2][arow] = f2tf32(va.z * 0.125f);
            As[ac4*4+3][arow] = f2tf32(va.w * 0.125f);
            int nrow = t4 >> 3, nc4 = t4 & 7;
            float4 vb = *(const float4*)&B[(size_t)(bcol + nrow) * HD + k0 + nc4*4];
            Bs[nc4*4+0][nrow] = f2tf32(vb.x);
            Bs[nc4*4+1][nrow] = f2tf32(vb.y);
            Bs[nc4*4+2][nrow] = f2tf32(vb.z);
            Bs[nc4*4+3][nrow] = f2tf32(vb.w);
        }
        __syncthreads();
#pragma unroll
        for (int ks = 0; ks < 4; ks++) {
            int kk = ks * 8;
            uint32_t a[2][4], b[8][2];
#pragma unroll
            for (int mt = 0; mt < 2; mt++) {
                int m0 = warpM*32 + mt*16;
                a[mt][0] = __float_as_uint(As[kk+tg  ][m0+g  ]);
                a[mt][1] = __float_as_uint(As[kk+tg  ][m0+g+8]);
                a[mt][2] = __float_as_uint(As[kk+tg+4][m0+g  ]);
                a[mt][3] = __float_as_uint(As[kk+tg+4][m0+g+8]);
            }
#pragma unroll
            for (int nt = 0; nt < 8; nt++) {
                int n0 = warpN*64 + nt*8;
                b[nt][0] = __float_as_uint(Bs[kk+tg  ][n0+g]);
                b[nt][1] = __float_as_uint(Bs[kk+tg+4][n0+g]);
            }
#pragma unroll
            for (int mt = 0; mt < 2; mt++)
#pragma unroll
                for (int nt = 0; nt < 8; nt++)
                    mma_tf32(acc[mt][nt], a[mt], b[nt]);
        }
        __syncthreads();
    }

#pragma unroll
    for (int mt = 0; mt < 2; mt++) {
#pragma unroll
        for (int nt = 0; nt < 8; nt++) {
            int r0 = brow + warpM*32 + mt*16 + g;
            int c0 = bcol + warpN*64 + nt*8 + tg*2;
#pragma unroll
            for (int e = 0; e < 4; e++) {
                int row = r0 + (e >> 1) * 8;
                int col = c0 + (e & 1);
                const float* rh = relh + ((size_t)bh * NSEQ + row) * 32;
                const float* rw = relw + ((size_t)bh * NSEQ + row) * 32;
                S[((size_t)bh * NSEQ + row) * NSEQ + col] =
                    acc[mt][nt][e] + rh[col >> 5] + rw[col & 31];
            }
        }
    }
}

// ---------------- AV: out = attn @ v (batched NN, 1024x64x1024) with head scatter -----
__global__ void __launch_bounds__(256)
attn_av_tc(const float* __restrict__ S, const float* __restrict__ v,
           float* __restrict__ out) {
    int bh = blockIdx.z;
    const float* A = S + (size_t)bh * NSEQ * NSEQ;
    const float* B = v + (size_t)bh * NSEQ * HD;
    __shared__ float As[32][136];
    __shared__ float Bs[32][72];
    int tx = threadIdx.x;
    int wid = tx >> 5, lane = tx & 31;
    int warpM = wid >> 1, warpN = wid & 1;
    int g = lane >> 2, tg = lane & 3;
    int brow = blockIdx.y * 128;

    float acc[2][4][4];
#pragma unroll
    for (int i = 0; i < 2; i++)
#pragma unroll
        for (int j = 0; j < 4; j++)
#pragma unroll
            for (int l = 0; l < 4; l++) acc[i][j][l] = 0.f;

    for (int k0 = 0; k0 < NSEQ; k0 += 32) {
#pragma unroll
        for (int i = 0; i < 4; i++) {
            int t4 = tx + i * 256;
            int arow = t4 >> 3, ac4 = t4 & 7;
            float4 va = *(const float4*)&A[(size_t)(brow + arow) * NSEQ + k0 + ac4*4];
            As[ac4*4+0][arow] = f2tf32(va.x);
            As[ac4*4+1][arow] = f2tf32(va.y);
            As[ac4*4+2][arow] = f2tf32(va.z);
            As[ac4*4+3][arow] = f2tf32(va.w);
        }
#pragma unroll
        for (int i = 0; i < 2; i++) {
            int t4 = tx + i * 256;
            int brk = t4 >> 4, bc4 = t4 & 15;
            float4 vb = *(const float4*)&B[(size_t)(k0 + brk) * HD + bc4*4];
            *(float4*)&Bs[brk][bc4*4] =
                make_float4(f2tf32(vb.x), f2tf32(vb.y), f2tf32(vb.z), f2tf32(vb.w));
        }
        __syncthreads();
#pragma unroll
        for (int ks = 0; ks < 4; ks++) {
            int kk = ks * 8;
            uint32_t a[2][4], b[4][2];
#pragma unroll
            for (int mt = 0; mt < 2; mt++) {
                int m0 = warpM*32 + mt*16;
                a[mt][0] = __float_as_uint(As[kk+tg  ][m0+g  ]);
                a[mt][1] = __float_as_uint(As[kk+tg  ][m0+g+8]);
                a[mt][2] = __float_as_uint(As[kk+tg+4][m0+g  ]);
                a[mt][3] = __float_as_uint(As[kk+tg+4][m0+g+8]);
            }
#pragma unroll
            for (int nt = 0; nt < 4; nt++) {
                int n0 = warpN*32 + nt*8;
                b[nt][0] = __float_as_uint(Bs[kk+tg  ][n0+g]);
                b[nt][1] = __float_as_uint(Bs[kk+tg+4][n0+g]);
            }
#pragma unroll
            for (int mt = 0; mt < 2; mt++)
#pragma unroll
                for (int nt = 0; nt < 4; nt++)
                    mma_tf32(acc[mt][nt], a[mt], b[nt]);
        }
        __syncthreads();
    }

    int b_ = bh / 12, head = bh % 12;
#pragma unroll
    for (int mt = 0; mt < 2; mt++) {
#pragma unroll
        for (int nt = 0; nt < 4; nt++) {
            int r0 = brow + warpM*32 + mt*16 + g;
            int c0 = warpN*32 + nt*8 + tg*2;
#pragma unroll
            for (int e = 0; e < 4; e++) {
                int row = r0 + (e >> 1) * 8;
                int col = c0 + (e & 1);
                out[((size_t)(b_ * NSEQ + row)) * CH + head * 64 + col] = acc[mt][nt][e];
            }
        }
    }
}

// ---------------- orchestration ----------------
extern "C" void kernel_launch(void* const* d_in, const int* in_sizes, int n_in,
                              void* d_out, int out_size) {
    const float* x         = (const float*)d_in[0];
    const float* conv_w    = (const float*)d_in[1];
    const float* conv_b    = (const float*)d_in[2];
    const float* pos_embed = (const float*)d_in[3];
    const float* ln1_w     = (const float*)d_in[4];
    const float* ln1_b     = (const float*)d_in[5];
    const float* qkv_w     = (const float*)d_in[6];
    const float* qkv_b     = (const float*)d_in[7];
    const float* proj_w    = (const float*)d_in[8];
    const float* proj_b    = (const float*)d_in[9];
    const float* rel_pos_h = (const float*)d_in[10];
    const float* rel_pos_w = (const float*)d_in[11];
    const float* ln2_w     = (const float*)d_in[12];
    const float* ln2_b     = (const float*)d_in[13];
    const float* fc1_w     = (const float*)d_in[14];
    const float* fc1_b     = (const float*)d_in[15];
    const float* fc2_w     = (const float*)d_in[16];
    const float* fc2_b     = (const float*)d_in[17];

    float *h, *ln, *colb, *wt, *q, *k, *v, *relh, *relw, *S, *ao, *mlp;
    cudaGetSymbolAddress((void**)&h,    g_h);
    cudaGetSymbolAddress((void**)&ln,   g_ln);
    cudaGetSymbolAddress((void**)&colb, g_col);
    cudaGetSymbolAddress((void**)&wt,   g_wt);
    cudaGetSymbolAddress((void**)&q,    g_q);
    cudaGetSymbolAddress((void**)&k,    g_k);
    cudaGetSymbolAddress((void**)&v,    g_v);
    cudaGetSymbolAddress((void**)&relh, g_relh);
    cudaGetSymbolAddress((void**)&relw, g_relw);
    cudaGetSymbolAddress((void**)&S,    g_S);
    cudaGetSymbolAddress((void**)&ao,   g_ao);
    cudaGetSymbolAddress((void**)&mlp,  g_mlp);

    im2col_k   <<<TOK*CH/256, 256>>>(x, colb);
    transpose_k<<<CH*CH/256, 256>>>(conv_w, wt);
    gemm_tc<0> <<<dim3(CH/128, TOK/128), 256>>>(colb, wt, conv_b, nullptr, h,
                                                nullptr, nullptr, TOK, CH, CH);
    addpos_k   <<<TOK*CH/256, 256>>>(h, pos_embed);

    for (int i = 0; i < 4; i++) {
        layernorm_k<<<TOK, 256>>>(h, ln1_w + i*CH, ln1_b + i*CH, ln);
        gemm_tc<3><<<dim3(QKVD/128, TOK/128), 256>>>(ln, qkv_w + (size_t)i*CH*QKVD,
                                                     qkv_b + i*QKVD, nullptr,
                                                     q, k, v, TOK, QKVD, CH);
        rel_k<<<BHD*NSEQ/8, 256>>>(q, rel_pos_h + i*63*HD, rel_pos_w + i*63*HD, relh, relw);
        attn_scores_tc<<<dim3(8, 8, BHD), 256>>>(q, k, relh, relw, S);
        softmax_k<<<BHD*NSEQ, 256>>>(S);
        attn_av_tc<<<dim3(1, 8, BHD), 256>>>(S, v, ao);
        gemm_tc<2><<<dim3(CH/128, TOK/128), 256>>>(ao, proj_w + (size_t)i*CH*CH,
                                                   proj_b + i*CH, h, h,
                                                   nullptr, nullptr, TOK, CH, CH);
        layernorm_k<<<TOK, 256>>>(h, ln2_w + i*CH, ln2_b + i*CH, ln);
        gemm_tc<1><<<dim3(MLPD/128, TOK/128), 256>>>(ln, fc1_w + (size_t)i*CH*MLPD,
                                                     fc1_b + i*MLPD, nullptr, mlp,
                                                     nullptr, nullptr, TOK, MLPD, CH);
        float* dst = (i == 3) ? (float*)d_out : h;
        gemm_tc<2><<<dim3(CH/128, TOK/128), 256>>>(mlp, fc2_w + (size_t)i*MLPD*CH,
                                                   fc2_b + i*CH, h, dst,
                                                   nullptr, nullptr, TOK, CH, MLPD);
    }
}

// round 5
// speedup vs baseline: 2.3745x; 1.1472x over previous
#include <cuda_runtime.h>
#include <math.h>
#include <stdint.h>

#define TOK  4096
#define CH   768
#define NSEQ 1024
#define BHD  48
#define HD   64
#define MLPD 3072
#define QKVD 2304

// ---------------- scratch (device globals; no allocations) ----------------
__device__ float g_h   [TOK*CH];
__device__ float g_ln  [TOK*CH];
__device__ float g_col [TOK*CH];
__device__ float g_wt  [CH*CH];
__device__ float g_q   [BHD*NSEQ*HD];
__device__ float g_k   [BHD*NSEQ*HD];
__device__ float g_v   [BHD*NSEQ*HD];
__device__ float g_relh[BHD*NSEQ*32];
__device__ float g_relw[BHD*NSEQ*32];
__device__ float g_ao  [TOK*CH];
__device__ float g_mlp [TOK*MLPD];

// ---------------- tf32 helpers ----------------
__device__ __forceinline__ float f2tf32(float x) {
    uint32_t u;
    asm("cvt.rna.tf32.f32 %0, %1;" : "=r"(u) : "f"(x));
    return __uint_as_float(u);
}

__device__ __forceinline__ void mma_tf32(float* c, const uint32_t* a, const uint32_t* b) {
    asm volatile(
        "mma.sync.aligned.m16n8k8.row.col.f32.tf32.tf32.f32 "
        "{%0,%1,%2,%3}, {%4,%5,%6,%7}, {%8,%9}, {%0,%1,%2,%3};\n"
        : "+f"(c[0]), "+f"(c[1]), "+f"(c[2]), "+f"(c[3])
        : "r"(a[0]), "r"(a[1]), "r"(a[2]), "r"(a[3]), "r"(b[0]), "r"(b[1]));
}

// ---------------- small helpers ----------------
__global__ void im2col_k(const float* __restrict__ x, float* __restrict__ out) {
    int idx = blockIdx.x * 256 + threadIdx.x;
    int token = idx / 768, kk = idx % 768;
    int ci = kk >> 8, r = kk & 255, py = r >> 4, px = r & 15;
    int b = token >> 10, g = token & 1023, gy = g >> 5, gx = g & 31;
    out[idx] = x[(((size_t)(b*3 + ci) * 512) + gy*16 + py) * 512 + gx*16 + px];
}

__global__ void transpose_k(const float* __restrict__ w, float* __restrict__ wt) {
    int idx = blockIdx.x * 256 + threadIdx.x;
    wt[(idx % 768) * 768 + (idx / 768)] = w[idx];
}

__global__ void addpos_k(float* __restrict__ h, const float* __restrict__ pos) {
    int idx = blockIdx.x * 256 + threadIdx.x;
    h[idx] += pos[idx % (NSEQ*CH)];
}

__global__ void rel_k(const float* __restrict__ q,
                      const float* __restrict__ rph, const float* __restrict__ rpw,
                      float* __restrict__ relh, float* __restrict__ relw) {
    int gw   = blockIdx.x * 8 + (threadIdx.x >> 5);
    int lane = threadIdx.x & 31;
    int bh = gw >> 10, qi = gw & 1023;
    int qy = qi >> 5, qx = qi & 31;
    const float* qp = q + ((size_t)bh * NSEQ + qi) * HD;
    const float* rh = rph + (qy - lane + 31) * HD;
    const float* rw = rpw + (qx - lane + 31) * HD;
    float sh = 0.f, sw = 0.f;
#pragma unroll
    for (int d = 0; d < HD; d++) { float qd = qp[d]; sh += qd * rh[d]; sw += qd * rw[d]; }
    relh[(size_t)gw * 32 + lane] = sh;
    relw[(size_t)gw * 32 + lane] = sw;
}

__global__ void layernorm_k(const float* __restrict__ x, const float* __restrict__ w,
                            const float* __restrict__ b, float* __restrict__ y) {
    int row = blockIdx.x;
    const float* xr = x + (size_t)row * CH;
    int t = threadIdx.x;
    float v0 = xr[t], v1 = xr[t+256], v2 = xr[t+512];
    __shared__ float red[256];
    red[t] = v0 + v1 + v2;
    __syncthreads();
    for (int o = 128; o > 0; o >>= 1) { if (t < o) red[t] += red[t+o]; __syncthreads(); }
    float mean = red[0] * (1.f/768.f);
    __syncthreads();
    float d0 = v0-mean, d1 = v1-mean, d2 = v2-mean;
    red[t] = d0*d0 + d1*d1 + d2*d2;
    __syncthreads();
    for (int o = 128; o > 0; o >>= 1) { if (t < o) red[t] += red[t+o]; __syncthreads(); }
    float rstd = rsqrtf(red[0] * (1.f/768.f) + 1e-5f);
    float* yr = y + (size_t)row * CH;
    yr[t]     = d0 * rstd * w[t]     + b[t];
    yr[t+256] = d1 * rstd * w[t+256] + b[t+256];
    yr[t+512] = d2 * rstd * w[t+512] + b[t+512];
}

// ---------------- tensor-core GEMM (NN) (unchanged from R2) ----------------
template <int EPI>
__global__ void __launch_bounds__(256)
gemm_tc(const float* __restrict__ A, const float* __restrict__ Bm,
        const float* __restrict__ bias, const float* __restrict__ res,
        float* __restrict__ C, float* __restrict__ k_out, float* __restrict__ v_out,
        int M, int N, int K) {
    __shared__ float As[32][136];
    __shared__ float Bs[32][136];
    int tx = threadIdx.x;
    int wid = tx >> 5, lane = tx & 31;
    int warpM = wid & 3, warpN = wid >> 2;
    int g = lane >> 2, tg = lane & 3;
    int brow = blockIdx.y * 128, bcol = blockIdx.x * 128;

    float acc[2][8][4];
#pragma unroll
    for (int i = 0; i < 2; i++)
#pragma unroll
        for (int j = 0; j < 8; j++)
#pragma unroll
            for (int l = 0; l < 4; l++) acc[i][j][l] = 0.f;

    for (int k0 = 0; k0 < K; k0 += 32) {
#pragma unroll
        for (int i = 0; i < 4; i++) {
            int t4 = tx + i * 256;
            int arow = t4 >> 3, ac4 = t4 & 7;
            float4 va = *(const float4*)&A[(size_t)(brow + arow) * K + k0 + ac4*4];
            As[ac4*4+0][arow] = f2tf32(va.x);
            As[ac4*4+1][arow] = f2tf32(va.y);
            As[ac4*4+2][arow] = f2tf32(va.z);
            As[ac4*4+3][arow] = f2tf32(va.w);
            int brk = t4 >> 5, bc4 = t4 & 31;
            float4 vb = *(const float4*)&Bm[(size_t)(k0 + brk) * N + bcol + bc4*4];
            *(float4*)&Bs[brk][bc4*4] =
                make_float4(f2tf32(vb.x), f2tf32(vb.y), f2tf32(vb.z), f2tf32(vb.w));
        }
        __syncthreads();
#pragma unroll
        for (int ks = 0; ks < 4; ks++) {
            int kk = ks * 8;
            uint32_t a[2][4], b[8][2];
#pragma unroll
            for (int mt = 0; mt < 2; mt++) {
                int m0 = warpM*32 + mt*16;
                a[mt][0] = __float_as_uint(As[kk+tg  ][m0+g  ]);
                a[mt][1] = __float_as_uint(As[kk+tg  ][m0+g+8]);
                a[mt][2] = __float_as_uint(As[kk+tg+4][m0+g  ]);
                a[mt][3] = __float_as_uint(As[kk+tg+4][m0+g+8]);
            }
#pragma unroll
            for (int nt = 0; nt < 8; nt++) {
                int n0 = warpN*64 + nt*8;
                b[nt][0] = __float_as_uint(Bs[kk+tg  ][n0+g]);
                b[nt][1] = __float_as_uint(Bs[kk+tg+4][n0+g]);
            }
#pragma unroll
            for (int mt = 0; mt < 2; mt++)
#pragma unroll
                for (int nt = 0; nt < 8; nt++)
                    mma_tf32(acc[mt][nt], a[mt], b[nt]);
        }
        __syncthreads();
    }

#pragma unroll
    for (int mt = 0; mt < 2; mt++) {
#pragma unroll
        for (int nt = 0; nt < 8; nt++) {
            int r0 = brow + warpM*32 + mt*16 + g;
            int c0 = bcol + warpN*64 + nt*8 + tg*2;
#pragma unroll
            for (int e = 0; e < 4; e++) {
                int row = r0 + (e >> 1) * 8;
                int col = c0 + (e & 1);
                float v = acc[mt][nt][e] + bias[col];
                if (EPI == 1) v = 0.5f * v * (1.f + erff(v * 0.70710678118f));
                if (EPI == 2) v += res[(size_t)row * N + col];
                if (EPI == 3) {
                    int which = col / 768, rem = col - which * 768;
                    int head = rem >> 6, d = rem & 63;
                    int b_ = row >> 10, n_ = row & 1023;
                    size_t dst = ((size_t)(b_*12 + head) * NSEQ + n_) * HD + d;
                    if (which == 0)      C[dst]     = v;
                    else if (which == 1) k_out[dst] = v;
                    else                 v_out[dst] = v;
                } else {
                    C[(size_t)row * N + col] = v;
                }
            }
        }
    }
}

// ---------------- fused flash attention (scores + rel bias + softmax + AV) -----------
// grid: (8 q-tiles, 48 bh). 256 threads. Dynamic smem.
#define OFF_Q    0
#define OFF_K    8704      /* 64x136 */
#define OFF_V    17408     /* 128x72 */
#define OFF_P    26624     /* 128x136 */
#define OFF_RH   44032     /* 128x33 */
#define OFF_RW   48256     /* 128x33 */
#define OFF_M    52480
#define OFF_L    52608
#define OFF_AL   52736
#define OFF_PMAX 52864     /* 2x128 */
#define OFF_PSUM 53120     /* 2x128 */
#define FA_SMEM_BYTES (53376*4)

__global__ void __launch_bounds__(256)
flash_attn(const float* __restrict__ q, const float* __restrict__ kg,
           const float* __restrict__ vg,
           const float* __restrict__ relh, const float* __restrict__ relw,
           float* __restrict__ out) {
    extern __shared__ float sm[];
    float* Qs = sm + OFF_Q;
    float* Ks = sm + OFF_K;
    float* Vs = sm + OFF_V;
    float* Ps = sm + OFF_P;
    float* RH = sm + OFF_RH;
    float* RW = sm + OFF_RW;
    float* Ms = sm + OFF_M;
    float* Ls = sm + OFF_L;
    float* Al = sm + OFF_AL;
    float* Pmax = sm + OFF_PMAX;
    float* Psum = sm + OFF_PSUM;

    int tx = threadIdx.x;
    int wid = tx >> 5, lane = tx & 31;
    int g = lane >> 2, tg = lane & 3;
    int qt = blockIdx.x, bh = blockIdx.y;
    int warpM  = wid & 3, warpN  = wid >> 2;   // S phase: 4x2 warps, 32x64 tiles
    int warpM2 = wid >> 1, warpN2 = wid & 1;   // O phase: 4x2 warps, 32x32 tiles

    const float* Qg  = q  + ((size_t)bh * NSEQ + qt * 128) * HD;
    const float* Kgp = kg + (size_t)bh * NSEQ * HD;
    const float* Vgp = vg + (size_t)bh * NSEQ * HD;

    // stage Q (scaled, tf32) as [k][m] pad136
#pragma unroll
    for (int i = 0; i < 8; i++) {
        int t4 = tx + i * 256;
        int row = t4 >> 4, c4 = t4 & 15;
        float4 va = *(const float4*)&Qg[row * HD + c4*4];
        Qs[(c4*4+0)*136 + row] = f2tf32(va.x * 0.125f);
        Qs[(c4*4+1)*136 + row] = f2tf32(va.y * 0.125f);
        Qs[(c4*4+2)*136 + row] = f2tf32(va.z * 0.125f);
        Qs[(c4*4+3)*136 + row] = f2tf32(va.w * 0.125f);
    }
    // stage rel tables, stride 33
    for (int idx = tx; idx < 4096; idx += 256) {
        int row = idx >> 5, c = idx & 31;
        size_t src = ((size_t)bh * NSEQ + qt * 128 + row) * 32 + c;
        RH[row*33 + c] = relh[src];
        RW[row*33 + c] = relw[src];
    }
    if (tx < 128) { Ms[tx] = -1e30f; Ls[tx] = 0.f; }

    float o[2][4][4];
#pragma unroll
    for (int a = 0; a < 2; a++)
#pragma unroll
        for (int b = 0; b < 4; b++)
#pragma unroll
            for (int c = 0; c < 4; c++) o[a][b][c] = 0.f;

    for (int kt = 0; kt < 8; kt++) {
        __syncthreads();   // prior readers of Ks/Vs/Ps done; Qs/RH ready on iter 0
        // load K tile [k=dim][n=key] tf32
#pragma unroll
        for (int i = 0; i < 8; i++) {
            int t4 = tx + i * 256;
            int row = t4 >> 4, c4 = t4 & 15;
            float4 vb = *(const float4*)&Kgp[(kt*128 + row) * HD + c4*4];
            Ks[(c4*4+0)*136 + row] = f2tf32(vb.x);
            Ks[(c4*4+1)*136 + row] = f2tf32(vb.y);
            Ks[(c4*4+2)*136 + row] = f2tf32(vb.z);
            Ks[(c4*4+3)*136 + row] = f2tf32(vb.w);
        }
        __syncthreads();

        // S = (scale*Q) @ K^T
        float s[2][8][4];
#pragma unroll
        for (int a = 0; a < 2; a++)
#pragma unroll
            for (int b = 0; b < 8; b++)
#pragma unroll
                for (int c = 0; c < 4; c++) s[a][b][c] = 0.f;
#pragma unroll
        for (int ks = 0; ks < 8; ks++) {
            int kk = ks * 8;
            uint32_t a[2][4], b[8][2];
#pragma unroll
            for (int mt = 0; mt < 2; mt++) {
                int m0 = warpM*32 + mt*16;
                a[mt][0] = __float_as_uint(Qs[(kk+tg  )*136 + m0+g  ]);
                a[mt][1] = __float_as_uint(Qs[(kk+tg  )*136 + m0+g+8]);
                a[mt][2] = __float_as_uint(Qs[(kk+tg+4)*136 + m0+g  ]);
                a[mt][3] = __float_as_uint(Qs[(kk+tg+4)*136 + m0+g+8]);
            }
#pragma unroll
            for (int nt = 0; nt < 8; nt++) {
                int n0 = warpN*64 + nt*8;
                b[nt][0] = __float_as_uint(Ks[(kk+tg  )*136 + n0+g]);
                b[nt][1] = __float_as_uint(Ks[(kk+tg+4)*136 + n0+g]);
            }
#pragma unroll
            for (int mt = 0; mt < 2; mt++)
#pragma unroll
                for (int nt = 0; nt < 8; nt++)
                    mma_tf32(s[mt][nt], a[mt], b[nt]);
        }

        // + rel bias; row-wise running max
        float rmax[2][2];
#pragma unroll
        for (int mt = 0; mt < 2; mt++)
#pragma unroll
            for (int rr = 0; rr < 2; rr++) {
                int row = warpM*32 + mt*16 + rr*8 + g;
                float rh0 = RH[row*33 + kt*4 + warpN*2];
                float rh1 = RH[row*33 + kt*4 + warpN*2 + 1];
                float mx = -1e30f;
#pragma unroll
                for (int nt = 0; nt < 8; nt++) {
#pragma unroll
                    for (int e1 = 0; e1 < 2; e1++) {
                        float rw = RW[row*33 + 8*(nt & 3) + 2*tg + e1];
                        float vv = s[mt][nt][rr*2 + e1] + ((nt < 4) ? rh0 : rh1) + rw;
                        s[mt][nt][rr*2 + e1] = vv;
                        mx = fmaxf(mx, vv);
                    }
                }
                rmax[mt][rr] = mx;
            }
#pragma unroll
        for (int mt = 0; mt < 2; mt++)
#pragma unroll
            for (int rr = 0; rr < 2; rr++) {
                float v = rmax[mt][rr];
                v = fmaxf(v, __shfl_xor_sync(0xffffffffu, v, 1));
                v = fmaxf(v, __shfl_xor_sync(0xffffffffu, v, 2));
                rmax[mt][rr] = v;
                if (tg == 0) Pmax[warpN*128 + warpM*32 + mt*16 + rr*8 + g] = v;
            }
        __syncthreads();
        if (tx < 128) {
            float m_old = Ms[tx];
            float m_new = fmaxf(m_old, fmaxf(Pmax[tx], Pmax[128 + tx]));
            float al = __expf(m_old - m_new);
            Al[tx] = al;
            Ls[tx] *= al;
            Ms[tx] = m_new;
        }
        __syncthreads();

        // exp, partial sums, write P transposed [k=key][m=row] (tf32)
        float rsum[2][2];
#pragma unroll
        for (int mt = 0; mt < 2; mt++)
#pragma unroll
            for (int rr = 0; rr < 2; rr++) {
                int rowl = warpM*32 + mt*16 + rr*8 + g;
                float mrow = Ms[rowl];
                float sum = 0.f;
#pragma unroll
                for (int nt = 0; nt < 8; nt++) {
#pragma unroll
                    for (int e1 = 0; e1 < 2; e1++) {
                        float p = __expf(s[mt][nt][rr*2 + e1] - mrow);
                        sum += p;
                        int col = warpN*64 + nt*8 + tg*2 + e1;
                        Ps[col*136 + rowl] = f2tf32(p);
                    }
                }
                rsum[mt][rr] = sum;
            }
#pragma unroll
        for (int mt = 0; mt < 2; mt++)
#pragma unroll
            for (int rr = 0; rr < 2; rr++) {
                float v = rsum[mt][rr];
                v += __shfl_xor_sync(0xffffffffu, v, 1);
                v += __shfl_xor_sync(0xffffffffu, v, 2);
                if (tg == 0) Psum[warpN*128 + warpM*32 + mt*16 + rr*8 + g] = v;
            }
        // load V tile [key][dim] pad72 (tf32)
#pragma unroll
        for (int i = 0; i < 8; i++) {
            int t4 = tx + i * 256;
            int row = t4 >> 4, c4 = t4 & 15;
            float4 vv = *(const float4*)&Vgp[(kt*128 + row) * HD + c4*4];
            *(float4*)&Vs[row*72 + c4*4] =
                make_float4(f2tf32(vv.x), f2tf32(vv.y), f2tf32(vv.z), f2tf32(vv.w));
        }
        __syncthreads();
        if (tx < 128) Ls[tx] += Psum[tx] + Psum[128 + tx];

        // rescale O, then O += P @ V
        float alv[2][2];
#pragma unroll
        for (int mt = 0; mt < 2; mt++)
#pragma unroll
            for (int rr = 0; rr < 2; rr++)
                alv[mt][rr] = Al[warpM2*32 + mt*16 + rr*8 + g];
#pragma unroll
        for (int mt = 0; mt < 2; mt++)
#pragma unroll
            for (int nt = 0; nt < 4; nt++)
#pragma unroll
                for (int e = 0; e < 4; e++)
                    o[mt][nt][e] *= alv[mt][e >> 1];
#pragma unroll
        for (int ks = 0; ks < 16; ks++) {
            int kk = ks * 8;
            uint32_t a[2][4], b[4][2];
#pragma unroll
            for (int mt = 0; mt < 2; mt++) {
                int m0 = warpM2*32 + mt*16;
                a[mt][0] = __float_as_uint(Ps[(kk+tg  )*136 + m0+g  ]);
                a[mt][1] = __float_as_uint(Ps[(kk+tg  )*136 + m0+g+8]);
                a[mt][2] = __float_as_uint(Ps[(kk+tg+4)*136 + m0+g  ]);
                a[mt][3] = __float_as_uint(Ps[(kk+tg+4)*136 + m0+g+8]);
            }
#pragma unroll
            for (int nt = 0; nt < 4; nt++) {
                int n0 = warpN2*32 + nt*8;
                b[nt][0] = __float_as_uint(Vs[(kk+tg  )*72 + n0+g]);
                b[nt][1] = __float_as_uint(Vs[(kk+tg+4)*72 + n0+g]);
            }
#pragma unroll
            for (int mt = 0; mt < 2; mt++)
#pragma unroll
                for (int nt = 0; nt < 4; nt++)
                    mma_tf32(o[mt][nt], a[mt], b[nt]);
        }
    }
    __syncthreads();

    // epilogue: O /= l, head-scatter to [token][768]
    int b_ = bh / 12, head = bh % 12;
    float linv[2][2];
#pragma unroll
    for (int mt = 0; mt < 2; mt++)
#pragma unroll
        for (int rr = 0; rr < 2; rr++)
            linv[mt][rr] = 1.f / Ls[warpM2*32 + mt*16 + rr*8 + g];
#pragma unroll
    for (int mt = 0; mt < 2; mt++) {
#pragma unroll
        for (int nt = 0; nt < 4; nt++) {
#pragma unroll
            for (int e = 0; e < 4; e++) {
                int r = warpM2*32 + mt*16 + (e >> 1)*8 + g;
                int c = warpN2*32 + nt*8 + tg*2 + (e & 1);
                out[((size_t)(b_ * NSEQ + qt*128 + r)) * CH + head*64 + c] =
                    o[mt][nt][e] * linv[mt][e >> 1];
            }
        }
    }
}

// ---------------- orchestration ----------------
extern "C" void kernel_launch(void* const* d_in, const int* in_sizes, int n_in,
                              void* d_out, int out_size) {
    const float* x         = (const float*)d_in[0];
    const float* conv_w    = (const float*)d_in[1];
    const float* conv_b    = (const float*)d_in[2];
    const float* pos_embed = (const float*)d_in[3];
    const float* ln1_w     = (const float*)d_in[4];
    const float* ln1_b     = (const float*)d_in[5];
    const float* qkv_w     = (const float*)d_in[6];
    const float* qkv_b     = (const float*)d_in[7];
    const float* proj_w    = (const float*)d_in[8];
    const float* proj_b    = (const float*)d_in[9];
    const float* rel_pos_h = (const float*)d_in[10];
    const float* rel_pos_w = (const float*)d_in[11];
    const float* ln2_w     = (const float*)d_in[12];
    const float* ln2_b     = (const float*)d_in[13];
    const float* fc1_w     = (const float*)d_in[14];
    const float* fc1_b     = (const float*)d_in[15];
    const float* fc2_w     = (const float*)d_in[16];
    const float* fc2_b     = (const float*)d_in[17];

    float *h, *ln, *colb, *wt, *q, *k, *v, *relh, *relw, *ao, *mlp;
    cudaGetSymbolAddress((void**)&h,    g_h);
    cudaGetSymbolAddress((void**)&ln,   g_ln);
    cudaGetSymbolAddress((void**)&colb, g_col);
    cudaGetSymbolAddress((void**)&wt,   g_wt);
    cudaGetSymbolAddress((void**)&q,    g_q);
    cudaGetSymbolAddress((void**)&k,    g_k);
    cudaGetSymbolAddress((void**)&v,    g_v);
    cudaGetSymbolAddress((void**)&relh, g_relh);
    cudaGetSymbolAddress((void**)&relw, g_relw);
    cudaGetSymbolAddress((void**)&ao,   g_ao);
    cudaGetSymbolAddress((void**)&mlp,  g_mlp);

    static bool attr_set = false;
    if (!attr_set) {
        cudaFuncSetAttribute(flash_attn, cudaFuncAttributeMaxDynamicSharedMemorySize,
                             FA_SMEM_BYTES);
        attr_set = true;
    }

    im2col_k   <<<TOK*CH/256, 256>>>(x, colb);
    transpose_k<<<CH*CH/256, 256>>>(conv_w, wt);
    gemm_tc<0> <<<dim3(CH/128, TOK/128), 256>>>(colb, wt, conv_b, nullptr, h,
                                                nullptr, nullptr, TOK, CH, CH);
    addpos_k   <<<TOK*CH/256, 256>>>(h, pos_embed);

    for (int i = 0; i < 4; i++) {
        layernorm_k<<<TOK, 256>>>(h, ln1_w + i*CH, ln1_b + i*CH, ln);
        gemm_tc<3><<<dim3(QKVD/128, TOK/128), 256>>>(ln, qkv_w + (size_t)i*CH*QKVD,
                                                     qkv_b + i*QKVD, nullptr,
                                                     q, k, v, TOK, QKVD, CH);
        rel_k<<<BHD*NSEQ/8, 256>>>(q, rel_pos_h + i*63*HD, rel_pos_w + i*63*HD, relh, relw);
        flash_attn<<<dim3(8, BHD), 256, FA_SMEM_BYTES>>>(q, k, v, relh, relw, ao);
        gemm_tc<2><<<dim3(CH/128, TOK/128), 256>>>(ao, proj_w + (size_t)i*CH*CH,
                                                   proj_b + i*CH, h, h,
                                                   nullptr, nullptr, TOK, CH, CH);
        layernorm_k<<<TOK, 256>>>(h, ln2_w + i*CH, ln2_b + i*CH, ln);
        gemm_tc<1><<<dim3(MLPD/128, TOK/128), 256>>>(ln, fc1_w + (size_t)i*CH*MLPD,
                                                     fc1_b + i*MLPD, nullptr, mlp,
                                                     nullptr, nullptr, TOK, MLPD, CH);
        float* dst = (i == 3) ? (float*)d_out : h;
        gemm_tc<2><<<dim3(CH/128, TOK/128), 256>>>(mlp, fc2_w + (size_t)i*MLPD*CH,
                                                   fc2_b + i*CH, h, dst,
                                                   nullptr, nullptr, TOK, CH, MLPD);
    }
}

// round 7
// speedup vs baseline: 2.6903x; 1.1330x over previous
#include <cuda_runtime.h>
#include <math.h>
#include <stdint.h>

#define TOK  4096
#define CH   768
#define NSEQ 1024
#define BHD  48
#define HD   64
#define MLPD 3072
#define QKVD 2304

// ---------------- scratch (device globals; no allocations) ----------------
__device__ float g_h   [TOK*CH];
__device__ float g_ln  [TOK*CH];
__device__ float g_col [TOK*CH];
__device__ float g_wt  [CH*CH];
__device__ float g_q   [BHD*NSEQ*HD];
__device__ float g_k   [BHD*NSEQ*HD];
__device__ float g_v   [BHD*NSEQ*HD];
__device__ float g_relh[BHD*NSEQ*32];
__device__ float g_relw[BHD*NSEQ*32];
__device__ float g_ao  [TOK*CH];
__device__ float g_mlp [TOK*MLPD];
// pre-rounded (tf32) weight copies
__device__ float g_wqkv[4*CH*QKVD];
__device__ float g_wproj[4*CH*CH];
__device__ float g_wfc1[4*CH*MLPD];
__device__ float g_wfc2[4*MLPD*CH];

// ---------------- tf32 helpers ----------------
__device__ __forceinline__ float f2tf32(float x) {
    uint32_t u;
    asm("cvt.rna.tf32.f32 %0, %1;" : "=r"(u) : "f"(x));
    return __uint_as_float(u);
}

__device__ __forceinline__ void mma_tf32(float* c, const uint32_t* a, const uint32_t* b) {
    asm volatile(
        "mma.sync.aligned.m16n8k8.row.col.f32.tf32.tf32.f32 "
        "{%0,%1,%2,%3}, {%4,%5,%6,%7}, {%8,%9}, {%0,%1,%2,%3};\n"
        : "+f"(c[0]), "+f"(c[1]), "+f"(c[2]), "+f"(c[3])
        : "r"(a[0]), "r"(a[1]), "r"(a[2]), "r"(a[3]), "r"(b[0]), "r"(b[1]));
}

__device__ __forceinline__ void cp16(uint32_t saddr, const void* g) {
    asm volatile("cp.async.ca.shared.global [%0], [%1], 16;" :: "r"(saddr), "l"(g));
}

// ---------------- small helpers ----------------
__global__ void round_copy_k(const float* __restrict__ x, float* __restrict__ y) {
    int idx = blockIdx.x * 256 + threadIdx.x;
    y[idx] = f2tf32(x[idx]);
}

__global__ void im2col_k(const float* __restrict__ x, float* __restrict__ out) {
    int idx = blockIdx.x * 256 + threadIdx.x;
    int token = idx / 768, kk = idx % 768;
    int ci = kk >> 8, r = kk & 255, py = r >> 4, px = r & 15;
    int b = token >> 10, g = token & 1023, gy = g >> 5, gx = g & 31;
    out[idx] = f2tf32(x[(((size_t)(b*3 + ci) * 512) + gy*16 + py) * 512 + gx*16 + px]);
}

__global__ void transpose_k(const float* __restrict__ w, float* __restrict__ wt) {
    int idx = blockIdx.x * 256 + threadIdx.x;
    wt[(idx % 768) * 768 + (idx / 768)] = f2tf32(w[idx]);
}

__global__ void addpos_k(float* __restrict__ h, const float* __restrict__ pos) {
    int idx = blockIdx.x * 256 + threadIdx.x;
    h[idx] += pos[idx % (NSEQ*CH)];
}

__global__ void rel_k(const float* __restrict__ q,
                      const float* __restrict__ rph, const float* __restrict__ rpw,
                      float* __restrict__ relh, float* __restrict__ relw) {
    int gw   = blockIdx.x * 8 + (threadIdx.x >> 5);
    int lane = threadIdx.x & 31;
    int bh = gw >> 10, qi = gw & 1023;
    int qy = qi >> 5, qx = qi & 31;
    const float* qp = q + ((size_t)bh * NSEQ + qi) * HD;
    const float* rh = rph + (qy - lane + 31) * HD;
    const float* rw = rpw + (qx - lane + 31) * HD;
    float sh = 0.f, sw = 0.f;
#pragma unroll
    for (int d = 0; d < HD; d++) { float qd = qp[d]; sh += qd * rh[d]; sw += qd * rw[d]; }
    relh[(size_t)gw * 32 + lane] = sh;
    relw[(size_t)gw * 32 + lane] = sw;
}

__global__ void layernorm_k(const float* __restrict__ x, const float* __restrict__ w,
                            const float* __restrict__ b, float* __restrict__ y) {
    int row = blockIdx.x;
    const float* xr = x + (size_t)row * CH;
    int t = threadIdx.x;
    float v0 = xr[t], v1 = xr[t+256], v2 = xr[t+512];
    __shared__ float red[256];
    red[t] = v0 + v1 + v2;
    __syncthreads();
    for (int o = 128; o > 0; o >>= 1) { if (t < o) red[t] += red[t+o]; __syncthreads(); }
    float mean = red[0] * (1.f/768.f);
    __syncthreads();
    float d0 = v0-mean, d1 = v1-mean, d2 = v2-mean;
    red[t] = d0*d0 + d1*d1 + d2*d2;
    __syncthreads();
    for (int o = 128; o > 0; o >>= 1) { if (t < o) red[t] += red[t+o]; __syncthreads(); }
    float rstd = rsqrtf(red[0] * (1.f/768.f) + 1e-5f);
    float* yr = y + (size_t)row * CH;
    yr[t]     = f2tf32(d0 * rstd * w[t]     + b[t]);
    yr[t+256] = f2tf32(d1 * rstd * w[t+256] + b[t+256]);
    yr[t+512] = f2tf32(d2 * rstd * w[t+512] + b[t+512]);
}

// ---------------- cp.async double-buffered tf32 GEMM (NN) ----------------------------
// A, B must already be tf32-rounded. smem: As[2][128][36], Bs[2][32][136] dynamic.
// EPI: 0 = bias, 1 = bias+GELU(rounded), 2 = bias+residual, 3 = qkv scatter
#define GEMM_SMEM_BYTES ((2*128*36 + 2*32*136) * 4)

template <int EPI>
__global__ void __launch_bounds__(256)
gemm_tc(const float* __restrict__ A, const float* __restrict__ Bm,
        const float* __restrict__ bias, const float* __restrict__ res,
        float* __restrict__ C, float* __restrict__ k_out, float* __restrict__ v_out,
        int M, int N, int K) {
    extern __shared__ float smem_dyn[];
    float* As = smem_dyn;                  // 2 stages of [128][36]
    float* Bs = smem_dyn + 2*128*36;       // 2 stages of [32][136]

    int tx = threadIdx.x;
    int wid = tx >> 5, lane = tx & 31;
    int warpM = wid & 3, warpN = wid >> 2;
    int g = lane >> 2, tg = lane & 3;
    int brow = blockIdx.y * 128, bcol = blockIdx.x * 128;

    uint32_t sA = (uint32_t)__cvta_generic_to_shared(As);
    uint32_t sB = (uint32_t)__cvta_generic_to_shared(Bs);

    float acc[2][8][4];
#pragma unroll
    for (int i = 0; i < 2; i++)
#pragma unroll
        for (int j = 0; j < 8; j++)
#pragma unroll
            for (int l = 0; l < 4; l++) acc[i][j][l] = 0.f;

    int KT = K >> 5;

    // A copy: 1024 float4 per stage; m = t4>>3, c4 = t4&7
    // B copy: 1024 float4 per stage; krow = t4>>5, nc4 = t4&31
#define LOAD_STAGE(st, k0)                                                        \
    {                                                                             \
        _Pragma("unroll")                                                         \
        for (int i = 0; i < 4; i++) {                                             \
            int t4 = tx + i * 256;                                                \
            int m = t4 >> 3, c4 = t4 & 7;                                         \
            cp16(sA + ((st)*128*36 + m*36 + c4*4)*4,                              \
                 &A[(size_t)(brow + m) * K + (k0) + c4*4]);                       \
            int krow = t4 >> 5, nc4 = t4 & 31;                                    \
            cp16(sB + ((st)*32*136 + krow*136 + nc4*4)*4,                         \
                 &Bm[(size_t)((k0) + krow) * N + bcol + nc4*4]);                  \
        }                                                                         \
    }

    LOAD_STAGE(0, 0);
    asm volatile("cp.async.commit_group;");

    for (int kt = 0; kt < KT; kt++) {
        if (kt + 1 < KT) {
            LOAD_STAGE((kt+1)&1, (kt+1)*32);
            asm volatile("cp.async.commit_group;");
            asm volatile("cp.async.wait_group 1;");
        } else {
            asm volatile("cp.async.wait_group 0;");
        }
        __syncthreads();

        const float* Ast = As + (kt&1)*128*36;
        const float* Bst = Bs + (kt&1)*32*136;
#pragma unroll
        for (int ks = 0; ks < 4; ks++) {
            int kk = ks * 8;
            uint32_t a[2][4], b[8][2];
#pragma unroll
            for (int mt = 0; mt < 2; mt++) {
                int m0 = warpM*32 + mt*16;
                a[mt][0] = __float_as_uint(Ast[(m0+g  )*36 + kk+tg  ]);
                a[mt][1] = __float_as_uint(Ast[(m0+g+8)*36 + kk+tg  ]);
                a[mt][2] = __float_as_uint(Ast[(m0+g  )*36 + kk+tg+4]);
                a[mt][3] = __float_as_uint(Ast[(m0+g+8)*36 + kk+tg+4]);
            }
#pragma unroll
            for (int nt = 0; nt < 8; nt++) {
                int n0 = warpN*64 + nt*8;
                b[nt][0] = __float_as_uint(Bst[(kk+tg  )*136 + n0+g]);
                b[nt][1] = __float_as_uint(Bst[(kk+tg+4)*136 + n0+g]);
            }
#pragma unroll
            for (int mt = 0; mt < 2; mt++)
#pragma unroll
                for (int nt = 0; nt < 8; nt++)
                    mma_tf32(acc[mt][nt], a[mt], b[nt]);
        }
        __syncthreads();
    }
#undef LOAD_STAGE

#pragma unroll
    for (int mt = 0; mt < 2; mt++) {
#pragma unroll
        for (int nt = 0; nt < 8; nt++) {
            int r0 = brow + warpM*32 + mt*16 + g;
            int c0 = bcol + warpN*64 + nt*8 + tg*2;
#pragma unroll
            for (int e = 0; e < 4; e++) {
                int row = r0 + (e >> 1) * 8;
                int col = c0 + (e & 1);
                float v = acc[mt][nt][e] + bias[col];
                if (EPI == 1) v = f2tf32(0.5f * v * (1.f + erff(v * 0.70710678118f)));
                if (EPI == 2) v += res[(size_t)row * N + col];
                if (EPI == 3) {
                    int which = col / 768, rem = col - which * 768;
                    int head = rem >> 6, d = rem & 63;
                    int b_ = row >> 10, n_ = row & 1023;
                    size_t dst = ((size_t)(b_*12 + head) * NSEQ + n_) * HD + d;
                    if (which == 0)      C[dst]     = v;
                    else if (which == 1) k_out[dst] = v;
                    else                 v_out[dst] = v;
                } else {
                    C[(size_t)row * N + col] = v;
                }
            }
        }
    }
}

// ---------------- fused flash attention (unchanged math; out rounded to tf32) --------
#define OFF_Q    0
#define OFF_K    8704
#define OFF_V    17408
#define OFF_P    26624
#define OFF_RH   44032
#define OFF_RW   48256
#define OFF_M    52480
#define OFF_L    52608
#define OFF_AL   52736
#define OFF_PMAX 52864
#define OFF_PSUM 53120
#define FA_SMEM_BYTES (53376*4)

__global__ void __launch_bounds__(256)
flash_attn(const float* __restrict__ q, const float* __restrict__ kg,
           const float* __restrict__ vg,
           const float* __restrict__ relh, const float* __restrict__ relw,
           float* __restrict__ out) {
    extern __shared__ float sm[];
    float* Qs = sm + OFF_Q;
    float* Ks = sm + OFF_K;
    float* Vs = sm + OFF_V;
    float* Ps = sm + OFF_P;
    float* RH = sm + OFF_RH;
    float* RW = sm + OFF_RW;
    float* Ms = sm + OFF_M;
    float* Ls = sm + OFF_L;
    float* Al = sm + OFF_AL;
    float* Pmax = sm + OFF_PMAX;
    float* Psum = sm + OFF_PSUM;

    int tx = threadIdx.x;
    int wid = tx >> 5, lane = tx & 31;
    int g = lane >> 2, tg = lane & 3;
    int qt = blockIdx.x, bh = blockIdx.y;
    int warpM  = wid & 3, warpN  = wid >> 2;
    int warpM2 = wid >> 1, warpN2 = wid & 1;

    const float* Qg  = q  + ((size_t)bh * NSEQ + qt * 128) * HD;
    const float* Kgp = kg + (size_t)bh * NSEQ * HD;
    const float* Vgp = vg + (size_t)bh * NSEQ * HD;

#pragma unroll
    for (int i = 0; i < 8; i++) {
        int t4 = tx + i * 256;
        int row = t4 >> 4, c4 = t4 & 15;
        float4 va = *(const float4*)&Qg[row * HD + c4*4];
        Qs[(c4*4+0)*136 + row] = f2tf32(va.x * 0.125f);
        Qs[(c4*4+1)*136 + row] = f2tf32(va.y * 0.125f);
        Qs[(c4*4+2)*136 + row] = f2tf32(va.z * 0.125f);
        Qs[(c4*4+3)*136 + row] = f2tf32(va.w * 0.125f);
    }
    for (int idx = tx; idx < 4096; idx += 256) {
        int row = idx >> 5, c = idx & 31;
        size_t src = ((size_t)bh * NSEQ + qt * 128 + row) * 32 + c;
        RH[row*33 + c] = relh[src];
        RW[row*33 + c] = relw[src];
    }
    if (tx < 128) { Ms[tx] = -1e30f; Ls[tx] = 0.f; }

    float o[2][4][4];
#pragma unroll
    for (int a = 0; a < 2; a++)
#pragma unroll
        for (int b = 0; b < 4; b++)
#pragma unroll
            for (int c = 0; c < 4; c++) o[a][b][c] = 0.f;

    for (int kt = 0; kt < 8; kt++) {
        __syncthreads();
#pragma unroll
        for (int i = 0; i < 8; i++) {
            int t4 = tx + i * 256;
            int row = t4 >> 4, c4 = t4 & 15;
            float4 vb = *(const float4*)&Kgp[(kt*128 + row) * HD + c4*4];
            Ks[(c4*4+0)*136 + row] = f2tf32(vb.x);
            Ks[(c4*4+1)*136 + row] = f2tf32(vb.y);
            Ks[(c4*4+2)*136 + row] = f2tf32(vb.z);
            Ks[(c4*4+3)*136 + row] = f2tf32(vb.w);
        }
        __syncthreads();

        float s[2][8][4];
#pragma unroll
        for (int a = 0; a < 2; a++)
#pragma unroll
            for (int b = 0; b < 8; b++)
#pragma unroll
                for (int c = 0; c < 4; c++) s[a][b][c] = 0.f;
#pragma unroll
        for (int ks = 0; ks < 8; ks++) {
            int kk = ks * 8;
            uint32_t a[2][4], b[8][2];
#pragma unroll
            for (int mt = 0; mt < 2; mt++) {
                int m0 = warpM*32 + mt*16;
                a[mt][0] = __float_as_uint(Qs[(kk+tg  )*136 + m0+g  ]);
                a[mt][1] = __float_as_uint(Qs[(kk+tg  )*136 + m0+g+8]);
                a[mt][2] = __float_as_uint(Qs[(kk+tg+4)*136 + m0+g  ]);
                a[mt][3] = __float_as_uint(Qs[(kk+tg+4)*136 + m0+g+8]);
            }
#pragma unroll
            for (int nt = 0; nt < 8; nt++) {
                int n0 = warpN*64 + nt*8;
                b[nt][0] = __float_as_uint(Ks[(kk+tg  )*136 + n0+g]);
                b[nt][1] = __float_as_uint(Ks[(kk+tg+4)*136 + n0+g]);
            }
#pragma unroll
            for (int mt = 0; mt < 2; mt++)
#pragma unroll
                for (int nt = 0; nt < 8; nt++)
                    mma_tf32(s[mt][nt], a[mt], b[nt]);
        }

        float rmax[2][2];
#pragma unroll
        for (int mt = 0; mt < 2; mt++)
#pragma unroll
            for (int rr = 0; rr < 2; rr++) {
                int row = warpM*32 + mt*16 + rr*8 + g;
                float rh0 = RH[row*33 + kt*4 + warpN*2];
                float rh1 = RH[row*33 + kt*4 + warpN*2 + 1];
                float mx = -1e30f;
#pragma unroll
                for (int nt = 0; nt < 8; nt++) {
#pragma unroll
                    for (int e1 = 0; e1 < 2; e1++) {
                        float rw = RW[row*33 + 8*(nt & 3) + 2*tg + e1];
                        float vv = s[mt][nt][rr*2 + e1] + ((nt < 4) ? rh0 : rh1) + rw;
                        s[mt][nt][rr*2 + e1] = vv;
                        mx = fmaxf(mx, vv);
                    }
                }
                rmax[mt][rr] = mx;
            }
#pragma unroll
        for (int mt = 0; mt < 2; mt++)
#pragma unroll
            for (int rr = 0; rr < 2; rr++) {
                float v = rmax[mt][rr];
                v = fmaxf(v, __shfl_xor_sync(0xffffffffu, v, 1));
                v = fmaxf(v, __shfl_xor_sync(0xffffffffu, v, 2));
                if (tg == 0) Pmax[warpN*128 + warpM*32 + mt*16 + rr*8 + g] = v;
            }
        __syncthreads();
        if (tx < 128) {
            float m_old = Ms[tx];
            float m_new = fmaxf(m_old, fmaxf(Pmax[tx], Pmax[128 + tx]));
            float al = __expf(m_old - m_new);
            Al[tx] = al;
            Ls[tx] *= al;
            Ms[tx] = m_new;
        }
        __syncthreads();

        float rsum[2][2];
#pragma unroll
        for (int mt = 0; mt < 2; mt++)
#pragma unroll
            for (int rr = 0; rr < 2; rr++) {
                int rowl = warpM*32 + mt*16 + rr*8 + g;
                float mrow = Ms[rowl];
                float sum = 0.f;
#pragma unroll
                for (int nt = 0; nt < 8; nt++) {
#pragma unroll
                    for (int e1 = 0; e1 < 2; e1++) {
                        float p = __expf(s[mt][nt][rr*2 + e1] - mrow);
                        sum += p;
                        int col = warpN*64 + nt*8 + tg*2 + e1;
                        Ps[col*136 + rowl] = f2tf32(p);
                    }
                }
                rsum[mt][rr] = sum;
            }
#pragma unroll
        for (int mt = 0; mt < 2; mt++)
#pragma unroll
            for (int rr = 0; rr < 2; rr++) {
                float v = rsum[mt][rr];
                v += __shfl_xor_sync(0xffffffffu, v, 1);
                v += __shfl_xor_sync(0xffffffffu, v, 2);
                if (tg == 0) Psum[warpN*128 + warpM*32 + mt*16 + rr*8 + g] = v;
            }
#pragma unroll
        for (int i = 0; i < 8; i++) {
            int t4 = tx + i * 256;
            int row = t4 >> 4, c4 = t4 & 15;
            float4 vv = *(const float4*)&Vgp[(kt*128 + row) * HD + c4*4];
            *(float4*)&Vs[row*72 + c4*4] =
                make_float4(f2tf32(vv.x), f2tf32(vv.y), f2tf32(vv.z), f2tf32(vv.w));
        }
        __syncthreads();
        if (tx < 128) Ls[tx] += Psum[tx] + Psum[128 + tx];

        float alv[2][2];
#pragma unroll
        for (int mt = 0; mt < 2; mt++)
#pragma unroll
            for (int rr = 0; rr < 2; rr++)
                alv[mt][rr] = Al[warpM2*32 + mt*16 + rr*8 + g];
#pragma unroll
        for (int mt = 0; mt < 2; mt++)
#pragma unroll
            for (int nt = 0; nt < 4; nt++)
#pragma unroll
                for (int e = 0; e < 4; e++)
                    o[mt][nt][e] *= alv[mt][e >> 1];
#pragma unroll
        for (int ks = 0; ks < 16; ks++) {
            int kk = ks * 8;
            uint32_t a[2][4], b[4][2];
#pragma unroll
            for (int mt = 0; mt < 2; mt++) {
                int m0 = warpM2*32 + mt*16;
                a[mt][0] = __float_as_uint(Ps[(kk+tg  )*136 + m0+g  ]);
                a[mt][1] = __float_as_uint(Ps[(kk+tg  )*136 + m0+g+8]);
                a[mt][2] = __float_as_uint(Ps[(kk+tg+4)*136 + m0+g  ]);
                a[mt][3] = __float_as_uint(Ps[(kk+tg+4)*136 + m0+g+8]);
            }
#pragma unroll
            for (int nt = 0; nt < 4; nt++) {
                int n0 = warpN2*32 + nt*8;
                b[nt][0] = __float_as_uint(Vs[(kk+tg  )*72 + n0+g]);
                b[nt][1] = __float_as_uint(Vs[(kk+tg+4)*72 + n0+g]);
            }
#pragma unroll
            for (int mt = 0; mt < 2; mt++)
#pragma unroll
                for (int nt = 0; nt < 4; nt++)
                    mma_tf32(o[mt][nt], a[mt], b[nt]);
        }
    }
    __syncthreads();

    int b_ = bh / 12, head = bh % 12;
    float linv[2][2];
#pragma unroll
    for (int mt = 0; mt < 2; mt++)
#pragma unroll
        for (int rr = 0; rr < 2; rr++)
            linv[mt][rr] = 1.f / Ls[warpM2*32 + mt*16 + rr*8 + g];
#pragma unroll
    for (int mt = 0; mt < 2; mt++) {
#pragma unroll
        for (int nt = 0; nt < 4; nt++) {
#pragma unroll
            for (int e = 0; e < 4; e++) {
                int r = warpM2*32 + mt*16 + (e >> 1)*8 + g;
                int c = warpN2*32 + nt*8 + tg*2 + (e & 1);
                out[((size_t)(b_ * NSEQ + qt*128 + r)) * CH + head*64 + c] =
                    f2tf32(o[mt][nt][e] * linv[mt][e >> 1]);
            }
        }
    }
}

// ---------------- orchestration ----------------
extern "C" void kernel_launch(void* const* d_in, const int* in_sizes, int n_in,
                              void* d_out, int out_size) {
    const float* x         = (const float*)d_in[0];
    const float* conv_w    = (const float*)d_in[1];
    const float* conv_b    = (const float*)d_in[2];
    const float* pos_embed = (const float*)d_in[3];
    const float* ln1_w     = (const float*)d_in[4];
    const float* ln1_b     = (const float*)d_in[5];
    const float* qkv_w     = (const float*)d_in[6];
    const float* qkv_b     = (const float*)d_in[7];
    const float* proj_w    = (const float*)d_in[8];
    const float* proj_b    = (const float*)d_in[9];
    const float* rel_pos_h = (const float*)d_in[10];
    const float* rel_pos_w = (const float*)d_in[11];
    const float* ln2_w     = (const float*)d_in[12];
    const float* ln2_b     = (const float*)d_in[13];
    const float* fc1_w     = (const float*)d_in[14];
    const float* fc1_b     = (const float*)d_in[15];
    const float* fc2_w     = (const float*)d_in[16];
    const float* fc2_b     = (const float*)d_in[17];

    float *h, *ln, *colb, *wt, *q, *k, *v, *relh, *relw, *ao, *mlp;
    float *wqkv, *wproj, *wfc1, *wfc2;
    cudaGetSymbolAddress((void**)&h,    g_h);
    cudaGetSymbolAddress((void**)&ln,   g_ln);
    cudaGetSymbolAddress((void**)&colb, g_col);
    cudaGetSymbolAddress((void**)&wt,   g_wt);
    cudaGetSymbolAddress((void**)&q,    g_q);
    cudaGetSymbolAddress((void**)&k,    g_k);
    cudaGetSymbolAddress((void**)&v,    g_v);
    cudaGetSymbolAddress((void**)&relh, g_relh);
    cudaGetSymbolAddress((void**)&relw, g_relw);
    cudaGetSymbolAddress((void**)&ao,   g_ao);
    cudaGetSymbolAddress((void**)&mlp,  g_mlp);
    cudaGetSymbolAddress((void**)&wqkv, g_wqkv);
    cudaGetSymbolAddress((void**)&wproj,g_wproj);
    cudaGetSymbolAddress((void**)&wfc1, g_wfc1);
    cudaGetSymbolAddress((void**)&wfc2, g_wfc2);

    static bool attr_set = false;
    if (!attr_set) {
        cudaFuncSetAttribute(flash_attn, cudaFuncAttributeMaxDynamicSharedMemorySize,
                             FA_SMEM_BYTES);
        cudaFuncSetAttribute(gemm_tc<0>, cudaFuncAttributeMaxDynamicSharedMemorySize,
                             GEMM_SMEM_BYTES);
        cudaFuncSetAttribute(gemm_tc<1>, cudaFuncAttributeMaxDynamicSharedMemorySize,
                             GEMM_SMEM_BYTES);
        cudaFuncSetAttribute(gemm_tc<2>, cudaFuncAttributeMaxDynamicSharedMemorySize,
                             GEMM_SMEM_BYTES);
        cudaFuncSetAttribute(gemm_tc<3>, cudaFuncAttributeMaxDynamicSharedMemorySize,
                             GEMM_SMEM_BYTES);
        attr_set = true;
    }

    // pre-round all weights to tf32 (exactly matches old per-tile .rna conversion)
    round_copy_k<<<4*CH*QKVD/256, 256>>>(qkv_w,  wqkv);
    round_copy_k<<<4*CH*CH/256,   256>>>(proj_w, wproj);
    round_copy_k<<<4*CH*MLPD/256, 256>>>(fc1_w,  wfc1);
    round_copy_k<<<4*MLPD*CH/256, 256>>>(fc2_w,  wfc2);

    im2col_k   <<<TOK*CH/256, 256>>>(x, colb);
    transpose_k<<<CH*CH/256, 256>>>(conv_w, wt);
    gemm_tc<0> <<<dim3(CH/128, TOK/128), 256, GEMM_SMEM_BYTES>>>(
        colb, wt, conv_b, nullptr, h, nullptr, nullptr, TOK, CH, CH);
    addpos_k   <<<TOK*CH/256, 256>>>(h, pos_embed);

    for (int i = 0; i < 4; i++) {
        layernorm_k<<<TOK, 256>>>(h, ln1_w + i*CH, ln1_b + i*CH, ln);
        gemm_tc<3><<<dim3(QKVD/128, TOK/128), 256, GEMM_SMEM_BYTES>>>(
            ln, wqkv + (size_t)i*CH*QKVD, qkv_b + i*QKVD, nullptr,
            q, k, v, TOK, QKVD, CH);
        rel_k<<<BHD*NSEQ/8, 256>>>(q, rel_pos_h + i*63*HD, rel_pos_w + i*63*HD, relh, relw);
        flash_attn<<<dim3(8, BHD), 256, FA_SMEM_BYTES>>>(q, k, v, relh, relw, ao);
        gemm_tc<2><<<dim3(CH/128, TOK/128), 256, GEMM_SMEM_BYTES>>>(
            ao, wproj + (size_t)i*CH*CH, proj_b + i*CH, h, h,
            nullptr, nullptr, TOK, CH, CH);
        layernorm_k<<<TOK, 256>>>(h, ln2_w + i*CH, ln2_b + i*CH, ln);
        gemm_tc<1><<<dim3(MLPD/128, TOK/128), 256, GEMM_SMEM_BYTES>>>(
            ln, wfc1 + (size_t)i*CH*MLPD, fc1_b + i*MLPD, nullptr, mlp,
            nullptr, nullptr, TOK, MLPD, CH);
        float* dst = (i == 3) ? (float*)d_out : h;
        gemm_tc<2><<<dim3(CH/128, TOK/128), 256, GEMM_SMEM_BYTES>>>(
            mlp, wfc2 + (size_t)i*MLPD*CH, fc2_b + i*CH, h, dst,
            nullptr, nullptr, TOK, CH, MLPD);
    }
}

// round 10
// speedup vs baseline: 3.0369x; 1.1288x over previous
#include <cuda_runtime.h>
#include <cuda_fp16.h>
#include <math.h>
#include <stdint.h>

#define TOK  4096
#define CH   768
#define NSEQ 1024
#define BHD  48
#define HD   64
#define MLPD 3072
#define QKVD 2304

// ---------------- scratch (device globals; no allocations) ----------------
__device__ float  g_h   [TOK*CH];
__device__ __half g_lnh [TOK*CH];
__device__ __half g_colh[TOK*CH];
__device__ __half g_wth [CH*CH];
__device__ float  g_q   [BHD*NSEQ*HD];
__device__ float  g_k   [BHD*NSEQ*HD];
__device__ float  g_v   [BHD*NSEQ*HD];
__device__ float  g_relh[BHD*NSEQ*32];
__device__ float  g_relw[BHD*NSEQ*32];
__device__ __half g_aoh [TOK*CH];
__device__ __half g_mlph[TOK*MLPD];
// transposed [n][k] half weights
__device__ __half g_wqkvh[4*CH*QKVD];
__device__ __half g_wprojh[4*CH*CH];
__device__ __half g_wfc1h[4*CH*MLPD];
__device__ __half g_wfc2h[4*MLPD*CH];

// ---------------- helpers ----------------
__device__ __forceinline__ float f2tf32(float x) {
    uint32_t u;
    asm("cvt.rna.tf32.f32 %0, %1;" : "=r"(u) : "f"(x));
    return __uint_as_float(u);
}

__device__ __forceinline__ void mma_tf32(float* c, const uint32_t* a, const uint32_t* b) {
    asm volatile(
        "mma.sync.aligned.m16n8k8.row.col.f32.tf32.tf32.f32 "
        "{%0,%1,%2,%3}, {%4,%5,%6,%7}, {%8,%9}, {%0,%1,%2,%3};\n"
        : "+f"(c[0]), "+f"(c[1]), "+f"(c[2]), "+f"(c[3])
        : "r"(a[0]), "r"(a[1]), "r"(a[2]), "r"(a[3]), "r"(b[0]), "r"(b[1]));
}

__device__ __forceinline__ void mma_f16(float* c, const uint32_t* a, const uint32_t* b) {
    asm volatile(
        "mma.sync.aligned.m16n8k16.row.col.f32.f16.f16.f32 "
        "{%0,%1,%2,%3}, {%4,%5,%6,%7}, {%8,%9}, {%0,%1,%2,%3};\n"
        : "+f"(c[0]), "+f"(c[1]), "+f"(c[2]), "+f"(c[3])
        : "r"(a[0]), "r"(a[1]), "r"(a[2]), "r"(a[3]), "r"(b[0]), "r"(b[1]));
}

__device__ __forceinline__ void cp16(uint32_t saddr, const void* g) {
    asm volatile("cp.async.ca.shared.global [%0], [%1], 16;" :: "r"(saddr), "l"(g));
}

// ---------------- prep kernels ----------------
// transpose-convert: w [K][N] fp32 -> wt [N][K] half.  grid (K/32, N/32, layers), block (32,8)
__global__ void wtrans_k(const float* __restrict__ w, __half* __restrict__ wt,
                         int K, int N) {
    __shared__ float t[32][33];
    size_t lo = (size_t)blockIdx.z * K * N;
    const float* wl = w + lo;
    __half* wtl = wt + lo;
    int k0 = blockIdx.x * 32, n0 = blockIdx.y * 32;
    int tx = threadIdx.x, ty = threadIdx.y;
#pragma unroll
    for (int r = 0; r < 32; r += 8)
        t[ty + r][tx] = wl[(size_t)(k0 + ty + r) * N + n0 + tx];
    __syncthreads();
#pragma unroll
    for (int r = 0; r < 32; r += 8)
        wtl[(size_t)(n0 + ty + r) * K + k0 + tx] = __float2half(t[tx][ty + r]);
}

__global__ void convhalf_k(const float* __restrict__ x, __half* __restrict__ y) {
    int idx = blockIdx.x * 256 + threadIdx.x;
    y[idx] = __float2half(x[idx]);
}

__global__ void im2col_k(const float* __restrict__ x, __half* __restrict__ out) {
    int idx = blockIdx.x * 256 + threadIdx.x;
    int token = idx / 768, kk = idx % 768;
    int ci = kk >> 8, r = kk & 255, py = r >> 4, px = r & 15;
    int b = token >> 10, g = token & 1023, gy = g >> 5, gx = g & 31;
    out[idx] = __float2half(
        x[(((size_t)(b*3 + ci) * 512) + gy*16 + py) * 512 + gx*16 + px]);
}

__global__ void rel_k(const float* __restrict__ q,
                      const float* __restrict__ rph, const float* __restrict__ rpw,
                      float* __restrict__ relh, float* __restrict__ relw) {
    int gw   = blockIdx.x * 8 + (threadIdx.x >> 5);
    int lane = threadIdx.x & 31;
    int bh = gw >> 10, qi = gw & 1023;
    int qy = qi >> 5, qx = qi & 31;
    const float* qp = q + ((size_t)bh * NSEQ + qi) * HD;
    const float* rh = rph + (qy - lane + 31) * HD;
    const float* rw = rpw + (qx - lane + 31) * HD;
    float sh = 0.f, sw = 0.f;
#pragma unroll
    for (int d = 0; d < HD; d++) { float qd = qp[d]; sh += qd * rh[d]; sw += qd * rw[d]; }
    relh[(size_t)gw * 32 + lane] = sh;
    relw[(size_t)gw * 32 + lane] = sw;
}

__global__ void layernorm_k(const float* __restrict__ x, const float* __restrict__ w,
                            const float* __restrict__ b, __half* __restrict__ y) {
    int row = blockIdx.x;
    const float* xr = x + (size_t)row * CH;
    int t = threadIdx.x;
    float v0 = xr[t], v1 = xr[t+256], v2 = xr[t+512];
    __shared__ float red[256];
    red[t] = v0 + v1 + v2;
    __syncthreads();
    for (int o = 128; o > 0; o >>= 1) { if (t < o) red[t] += red[t+o]; __syncthreads(); }
    float mean = red[0] * (1.f/768.f);
    __syncthreads();
    float d0 = v0-mean, d1 = v1-mean, d2 = v2-mean;
    red[t] = d0*d0 + d1*d1 + d2*d2;
    __syncthreads();
    for (int o = 128; o > 0; o >>= 1) { if (t < o) red[t] += red[t+o]; __syncthreads(); }
    float rstd = rsqrtf(red[0] * (1.f/768.f) + 1e-5f);
    __half* yr = y + (size_t)row * CH;
    yr[t]     = __float2half(d0 * rstd * w[t]     + b[t]);
    yr[t+256] = __float2half(d1 * rstd * w[t+256] + b[t+256]);
    yr[t+512] = __float2half(d2 * rstd * w[t+512] + b[t+512]);
}

// ---------------- fp16 cp.async double-buffered GEMM ---------------------------------
// A [M][K] half row-major, Bt [N][K] half n-major. C = A @ Bt^T + bias.
// EPI: 1 = bias+GELU -> half Ch, 2 = bias+residual -> fp32 C,
//      3 = qkv scatter -> fp32 q/k/v, 4 = bias + pos-embed add -> fp32 C
template <int EPI>
__global__ void __launch_bounds__(256)
gemm_h(const __half* __restrict__ A, const __half* __restrict__ Bt,
       const float* __restrict__ bias, const float* __restrict__ res,
       float* __restrict__ C, __half* __restrict__ Ch,
       float* __restrict__ k_out, float* __restrict__ v_out,
       int M, int N, int K) {
    __shared__ __half As[2][128][40];
    __shared__ __half Bs[2][128][40];

    int tx = threadIdx.x;
    int wid = tx >> 5, lane = tx & 31;
    int warpM = wid & 3, warpN = wid >> 2;
    int g = lane >> 2, tg = lane & 3;
    int brow = blockIdx.y * 128, bcol = blockIdx.x * 128;

    uint32_t sA = (uint32_t)__cvta_generic_to_shared(&As[0][0][0]);
    uint32_t sB = (uint32_t)__cvta_generic_to_shared(&Bs[0][0][0]);

    float acc[2][8][4];
#pragma unroll
    for (int i = 0; i < 2; i++)
#pragma unroll
        for (int j = 0; j < 8; j++)
#pragma unroll
            for (int l = 0; l < 4; l++) acc[i][j][l] = 0.f;

    int KT = K >> 5;

    // per stage: A 512 x 16B chunks (row m: 4 chunks), B same. 4 cp16/thread.
#define LOAD_STAGE(st, k0)                                                        \
    {                                                                             \
        _Pragma("unroll")                                                         \
        for (int i = 0; i < 2; i++) {                                             \
            int t4 = tx + i * 256;                                                \
            int m = t4 >> 2, c8 = t4 & 3;                                         \
            cp16(sA + ((st)*128*40 + m*40 + c8*8)*2,                              \
                 &A[(size_t)(brow + m) * K + (k0) + c8*8]);                       \
            cp16(sB + ((st)*128*40 + m*40 + c8*8)*2,                              \
                 &Bt[(size_t)(bcol + m) * K + (k0) + c8*8]);                      \
        }                                                                         \
    }

    LOAD_STAGE(0, 0);
    asm volatile("cp.async.commit_group;");

    for (int kt = 0; kt < KT; kt++) {
        if (kt + 1 < KT) {
            LOAD_STAGE((kt+1)&1, (kt+1)*32);
            asm volatile("cp.async.commit_group;");
            asm volatile("cp.async.wait_group 1;");
        } else {
            asm volatile("cp.async.wait_group 0;");
        }
        __syncthreads();

        const __half* Ast = &As[kt&1][0][0];
        const __half* Bst = &Bs[kt&1][0][0];
#pragma unroll
        for (int kk = 0; kk < 32; kk += 16) {
            uint32_t a[2][4], b[8][2];
#pragma unroll
            for (int mt = 0; mt < 2; mt++) {
                int m0 = warpM*32 + mt*16;
                a[mt][0] = *(const uint32_t*)&Ast[(m0+g  )*40 + kk + 2*tg    ];
                a[mt][1] = *(const uint32_t*)&Ast[(m0+g+8)*40 + kk + 2*tg    ];
                a[mt][2] = *(const uint32_t*)&Ast[(m0+g  )*40 + kk + 2*tg + 8];
                a[mt][3] = *(const uint32_t*)&Ast[(m0+g+8)*40 + kk + 2*tg + 8];
            }
#pragma unroll
            for (int nt = 0; nt < 8; nt++) {
                int n0 = warpN*64 + nt*8;
                b[nt][0] = *(const uint32_t*)&Bst[(n0+g)*40 + kk + 2*tg    ];
                b[nt][1] = *(const uint32_t*)&Bst[(n0+g)*40 + kk + 2*tg + 8];
            }
#pragma unroll
            for (int mt = 0; mt < 2; mt++)
#pragma unroll
                for (int nt = 0; nt < 8; nt++)
                    mma_f16(acc[mt][nt], a[mt], b[nt]);
        }
        __syncthreads();
    }
#undef LOAD_STAGE

#pragma unroll
    for (int mt = 0; mt < 2; mt++) {
#pragma unroll
        for (int nt = 0; nt < 8; nt++) {
            int r0 = brow + warpM*32 + mt*16 + g;
            int c0 = bcol + warpN*64 + nt*8 + tg*2;
#pragma unroll
            for (int e = 0; e < 4; e++) {
                int row = r0 + (e >> 1) * 8;
                int col = c0 + (e & 1);
                float v = acc[mt][nt][e] + bias[col];
                if (EPI == 1) {
                    v = 0.5f * v * (1.f + erff(v * 0.70710678118f));
                    Ch[(size_t)row * N + col] = __float2half(v);
                } else if (EPI == 2) {
                    C[(size_t)row * N + col] = v + res[(size_t)row * N + col];
                } else if (EPI == 3) {
                    int which = col / 768, rem = col - which * 768;
                    int head = rem >> 6, d = rem & 63;
                    int b_ = row >> 10, n_ = row & 1023;
                    size_t dst = ((size_t)(b_*12 + head) * NSEQ + n_) * HD + d;
                    if (which == 0)      C[dst]     = v;
                    else if (which == 1) k_out[dst] = v;
                    else                 v_out[dst] = v;
                } else if (EPI == 4) {
                    C[(size_t)row * N + col] = v + res[(size_t)(row & 1023) * CH + col];
                } else {
                    C[(size_t)row * N + col] = v;
                }
            }
        }
    }
}

// ---------------- fused flash attention (tf32 internals; half output) ----------------
#define OFF_Q    0
#define OFF_K    8704
#define OFF_V    17408
#define OFF_P    26624
#define OFF_RH   44032
#define OFF_RW   48256
#define OFF_M    52480
#define OFF_L    52608
#define OFF_AL   52736
#define OFF_PMAX 52864
#define OFF_PSUM 53120
#define FA_SMEM_BYTES (53376*4)

__global__ void __launch_bounds__(256)
flash_attn(const float* __restrict__ q, const float* __restrict__ kg,
           const float* __restrict__ vg,
           const float* __restrict__ relh, const float* __restrict__ relw,
           __half* __restrict__ out) {
    extern __shared__ float sm[];
    float* Qs = sm + OFF_Q;
    float* Ks = sm + OFF_K;
    float* Vs = sm + OFF_V;
    float* Ps = sm + OFF_P;
    float* RH = sm + OFF_RH;
    float* RW = sm + OFF_RW;
    float* Ms = sm + OFF_M;
    float* Ls = sm + OFF_L;
    float* Al = sm + OFF_AL;
    float* Pmax = sm + OFF_PMAX;
    float* Psum = sm + OFF_PSUM;

    int tx = threadIdx.x;
    int wid = tx >> 5, lane = tx & 31;
    int g = lane >> 2, tg = lane & 3;
    int qt = blockIdx.x, bh = blockIdx.y;
    int warpM  = wid & 3, warpN  = wid >> 2;
    int warpM2 = wid >> 1, warpN2 = wid & 1;

    const float* Qg  = q  + ((size_t)bh * NSEQ + qt * 128) * HD;
    const float* Kgp = kg + (size_t)bh * NSEQ * HD;
    const float* Vgp = vg + (size_t)bh * NSEQ * HD;

#pragma unroll
    for (int i = 0; i < 8; i++) {
        int t4 = tx + i * 256;
        int row = t4 >> 4, c4 = t4 & 15;
        float4 va = *(const float4*)&Qg[row * HD + c4*4];
        Qs[(c4*4+0)*136 + row] = f2tf32(va.x * 0.125f);
        Qs[(c4*4+1)*136 + row] = f2tf32(va.y * 0.125f);
        Qs[(c4*4+2)*136 + row] = f2tf32(va.z * 0.125f);
        Qs[(c4*4+3)*136 + row] = f2tf32(va.w * 0.125f);
    }
    for (int idx = tx; idx < 4096; idx += 256) {
        int row = idx >> 5, c = idx & 31;
        size_t src = ((size_t)bh * NSEQ + qt * 128 + row) * 32 + c;
        RH[row*33 + c] = relh[src];
        RW[row*33 + c] = relw[src];
    }
    if (tx < 128) { Ms[tx] = -1e30f; Ls[tx] = 0.f; }

    float o[2][4][4];
#pragma unroll
    for (int a = 0; a < 2; a++)
#pragma unroll
        for (int b = 0; b < 4; b++)
#pragma unroll
            for (int c = 0; c < 4; c++) o[a][b][c] = 0.f;

    for (int kt = 0; kt < 8; kt++) {
        __syncthreads();
#pragma unroll
        for (int i = 0; i < 8; i++) {
            int t4 = tx + i * 256;
            int row = t4 >> 4, c4 = t4 & 15;
            float4 vb = *(const float4*)&Kgp[(kt*128 + row) * HD + c4*4];
            Ks[(c4*4+0)*136 + row] = f2tf32(vb.x);
            Ks[(c4*4+1)*136 + row] = f2tf32(vb.y);
            Ks[(c4*4+2)*136 + row] = f2tf32(vb.z);
            Ks[(c4*4+3)*136 + row] = f2tf32(vb.w);
        }
        __syncthreads();

        float s[2][8][4];
#pragma unroll
        for (int a = 0; a < 2; a++)
#pragma unroll
            for (int b = 0; b < 8; b++)
#pragma unroll
                for (int c = 0; c < 4; c++) s[a][b][c] = 0.f;
#pragma unroll
        for (int ks = 0; ks < 8; ks++) {
            int kk = ks * 8;
            uint32_t a[2][4], b[8][2];
#pragma unroll
            for (int mt = 0; mt < 2; mt++) {
                int m0 = warpM*32 + mt*16;
                a[mt][0] = __float_as_uint(Qs[(kk+tg  )*136 + m0+g  ]);
                a[mt][1] = __float_as_uint(Qs[(kk+tg  )*136 + m0+g+8]);
                a[mt][2] = __float_as_uint(Qs[(kk+tg+4)*136 + m0+g  ]);
                a[mt][3] = __float_as_uint(Qs[(kk+tg+4)*136 + m0+g+8]);
            }
#pragma unroll
            for (int nt = 0; nt < 8; nt++) {
                int n0 = warpN*64 + nt*8;
                b[nt][0] = __float_as_uint(Ks[(kk+tg  )*136 + n0+g]);
                b[nt][1] = __float_as_uint(Ks[(kk+tg+4)*136 + n0+g]);
            }
#pragma unroll
            for (int mt = 0; mt < 2; mt++)
#pragma unroll
                for (int nt = 0; nt < 8; nt++)
                    mma_tf32(s[mt][nt], a[mt], b[nt]);
        }

        float rmax[2][2];
#pragma unroll
        for (int mt = 0; mt < 2; mt++)
#pragma unroll
            for (int rr = 0; rr < 2; rr++) {
                int row = warpM*32 + mt*16 + rr*8 + g;
                float rh0 = RH[row*33 + kt*4 + warpN*2];
                float rh1 = RH[row*33 + kt*4 + warpN*2 + 1];
                float mx = -1e30f;
#pragma unroll
                for (int nt = 0; nt < 8; nt++) {
#pragma unroll
                    for (int e1 = 0; e1 < 2; e1++) {
                        float rw = RW[row*33 + 8*(nt & 3) + 2*tg + e1];
                        float vv = s[mt][nt][rr*2 + e1] + ((nt < 4) ? rh0 : rh1) + rw;
                        s[mt][nt][rr*2 + e1] = vv;
                        mx = fmaxf(mx, vv);
                    }
                }
                rmax[mt][rr] = mx;
            }
#pragma unroll
        for (int mt = 0; mt < 2; mt++)
#pragma unroll
            for (int rr = 0; rr < 2; rr++) {
                float v = rmax[mt][rr];
                v = fmaxf(v, __shfl_xor_sync(0xffffffffu, v, 1));
                v = fmaxf(v, __shfl_xor_sync(0xffffffffu, v, 2));
                if (tg == 0) Pmax[warpN*128 + warpM*32 + mt*16 + rr*8 + g] = v;
            }
        __syncthreads();
        if (tx < 128) {
            float m_old = Ms[tx];
            float m_new = fmaxf(m_old, fmaxf(Pmax[tx], Pmax[128 + tx]));
            float al = __expf(m_old - m_new);
            Al[tx] = al;
            Ls[tx] *= al;
            Ms[tx] = m_new;
        }
        __syncthreads();

        float rsum[2][2];
#pragma unroll
        for (int mt = 0; mt < 2; mt++)
#pragma unroll
            for (int rr = 0; rr < 2; rr++) {
                int rowl = warpM*32 + mt*16 + rr*8 + g;
                float mrow = Ms[rowl];
                float sum = 0.f;
#pragma unroll
                for (int nt = 0; nt < 8; nt++) {
#pragma unroll
                    for (int e1 = 0; e1 < 2; e1++) {
                        float p = __expf(s[mt][nt][rr*2 + e1] - mrow);
                        sum += p;
                        int col = warpN*64 + nt*8 + tg*2 + e1;
                        Ps[col*136 + rowl] = f2tf32(p);
                    }
                }
                rsum[mt][rr] = sum;
            }
#pragma unroll
        for (int mt = 0; mt < 2; mt++)
#pragma unroll
            for (int rr = 0; rr < 2; rr++) {
                float v = rsum[mt][rr];
                v += __shfl_xor_sync(0xffffffffu, v, 1);
                v += __shfl_xor_sync(0xffffffffu, v, 2);
                if (tg == 0) Psum[warpN*128 + warpM*32 + mt*16 + rr*8 + g] = v;
            }
#pragma unroll
        for (int i = 0; i < 8; i++) {
            int t4 = tx + i * 256;
            int row = t4 >> 4, c4 = t4 & 15;
            float4 vv = *(const float4*)&Vgp[(kt*128 + row) * HD + c4*4];
            *(float4*)&Vs[row*72 + c4*4] =
                make_float4(f2tf32(vv.x), f2tf32(vv.y), f2tf32(vv.z), f2tf32(vv.w));
        }
        __syncthreads();
        if (tx < 128) Ls[tx] += Psum[tx] + Psum[128 + tx];

        float alv[2][2];
#pragma unroll
        for (int mt = 0; mt < 2; mt++)
#pragma unroll
            for (int rr = 0; rr < 2; rr++)
                alv[mt][rr] = Al[warpM2*32 + mt*16 + rr*8 + g];
#pragma unroll
        for (int mt = 0; mt < 2; mt++)
#pragma unroll
            for (int nt = 0; nt < 4; nt++)
#pragma unroll
                for (int e = 0; e < 4; e++)
                    o[mt][nt][e] *= alv[mt][e >> 1];
#pragma unroll
        for (int ks = 0; ks < 16; ks++) {
            int kk = ks * 8;
            uint32_t a[2][4], b[4][2];
#pragma unroll
            for (int mt = 0; mt < 2; mt++) {
                int m0 = warpM2*32 + mt*16;
                a[mt][0] = __float_as_uint(Ps[(kk+tg  )*136 + m0+g  ]);
                a[mt][1] = __float_as_uint(Ps[(kk+tg  )*136 + m0+g+8]);
                a[mt][2] = __float_as_uint(Ps[(kk+tg+4)*136 + m0+g  ]);
                a[mt][3] = __float_as_uint(Ps[(kk+tg+4)*136 + m0+g+8]);
            }
#pragma unroll
            for (int nt = 0; nt < 4; nt++) {
                int n0 = warpN2*32 + nt*8;
                b[nt][0] = __float_as_uint(Vs[(kk+tg  )*72 + n0+g]);
                b[nt][1] = __float_as_uint(Vs[(kk+tg+4)*72 + n0+g]);
            }
#pragma unroll
            for (int mt = 0; mt < 2; mt++)
#pragma unroll
                for (int nt = 0; nt < 4; nt++)
                    mma_tf32(o[mt][nt], a[mt], b[nt]);
        }
    }
    __syncthreads();

    int b_ = bh / 12, head = bh % 12;
    float linv[2][2];
#pragma unroll
    for (int mt = 0; mt < 2; mt++)
#pragma unroll
        for (int rr = 0; rr < 2; rr++)
            linv[mt][rr] = 1.f / Ls[warpM2*32 + mt*16 + rr*8 + g];
#pragma unroll
    for (int mt = 0; mt < 2; mt++) {
#pragma unroll
        for (int nt = 0; nt < 4; nt++) {
#pragma unroll
            for (int e = 0; e < 4; e++) {
                int r = warpM2*32 + mt*16 + (e >> 1)*8 + g;
                int c = warpN2*32 + nt*8 + tg*2 + (e & 1);
                out[((size_t)(b_ * NSEQ + qt*128 + r)) * CH + head*64 + c] =
                    __float2half(o[mt][nt][e] * linv[mt][e >> 1]);
            }
        }
    }
}

// ---------------- orchestration ----------------
extern "C" void kernel_launch(void* const* d_in, const int* in_sizes, int n_in,
                              void* d_out, int out_size) {
    const float* x         = (const float*)d_in[0];
    const float* conv_w    = (const float*)d_in[1];
    const float* conv_b    = (const float*)d_in[2];
    const float* pos_embed = (const float*)d_in[3];
    const float* ln1_w     = (const float*)d_in[4];
    const float* ln1_b     = (const float*)d_in[5];
    const float* qkv_w     = (const float*)d_in[6];
    const float* qkv_b     = (const float*)d_in[7];
    const float* proj_w    = (const float*)d_in[8];
    const float* proj_b    = (const float*)d_in[9];
    const float* rel_pos_h = (const float*)d_in[10];
    const float* rel_pos_w = (const float*)d_in[11];
    const float* ln2_w     = (const float*)d_in[12];
    const float* ln2_b     = (const float*)d_in[13];
    const float* fc1_w     = (const float*)d_in[14];
    const float* fc1_b     = (const float*)d_in[15];
    const float* fc2_w     = (const float*)d_in[16];
    const float* fc2_b     = (const float*)d_in[17];

    float *h, *q, *k, *v, *relh, *relw;
    __half *lnh, *colh, *wth, *aoh, *mlph, *wqkvh, *wprojh, *wfc1h, *wfc2h;
    cudaGetSymbolAddress((void**)&h,     g_h);
    cudaGetSymbolAddress((void**)&lnh,   g_lnh);
    cudaGetSymbolAddress((void**)&colh,  g_colh);
    cudaGetSymbolAddress((void**)&wth,   g_wth);
    cudaGetSymbolAddress((void**)&q,     g_q);
    cudaGetSymbolAddress((void**)&k,     g_k);
    cudaGetSymbolAddress((void**)&v,     g_v);
    cudaGetSymbolAddress((void**)&relh,  g_relh);
    cudaGetSymbolAddress((void**)&relw,  g_relw);
    cudaGetSymbolAddress((void**)&aoh,   g_aoh);
    cudaGetSymbolAddress((void**)&mlph,  g_mlph);
    cudaGetSymbolAddress((void**)&wqkvh, g_wqkvh);
    cudaGetSymbolAddress((void**)&wprojh,g_wprojh);
    cudaGetSymbolAddress((void**)&wfc1h, g_wfc1h);
    cudaGetSymbolAddress((void**)&wfc2h, g_wfc2h);

    static bool attr_set = false;
    if (!attr_set) {
        cudaFuncSetAttribute(flash_attn, cudaFuncAttributeMaxDynamicSharedMemorySize,
                             FA_SMEM_BYTES);
        attr_set = true;
    }

    // weight prep: transpose + half-convert
    dim3 tb(32, 8);
    wtrans_k<<<dim3(CH/32,  QKVD/32, 4), tb>>>(qkv_w,  wqkvh, CH,   QKVD);
    wtrans_k<<<dim3(CH/32,  CH/32,   4), tb>>>(proj_w, wprojh, CH,  CH);
    wtrans_k<<<dim3(CH/32,  MLPD/32, 4), tb>>>(fc1_w,  wfc1h, CH,   MLPD);
    wtrans_k<<<dim3(MLPD/32,CH/32,   4), tb>>>(fc2_w,  wfc2h, MLPD, CH);
    convhalf_k<<<CH*CH/256, 256>>>(conv_w, wth);  // conv_w already [n][k]

    im2col_k<<<TOK*CH/256, 256>>>(x, colh);
    gemm_h<4><<<dim3(CH/128, TOK/128), 256>>>(
        colh, wth, conv_b, pos_embed, h, nullptr, nullptr, nullptr, TOK, CH, CH);

    for (int i = 0; i < 4; i++) {
        layernorm_k<<<TOK, 256>>>(h, ln1_w + i*CH, ln1_b + i*CH, lnh);
        gemm_h<3><<<dim3(QKVD/128, TOK/128), 256>>>(
            lnh, wqkvh + (size_t)i*CH*QKVD, qkv_b + i*QKVD, nullptr,
            q, nullptr, k, v, TOK, QKVD, CH);
        rel_k<<<BHD*NSEQ/8, 256>>>(q, rel_pos_h + i*63*HD, rel_pos_w + i*63*HD,
                                   relh, relw);
        flash_attn<<<dim3(8, BHD), 256, FA_SMEM_BYTES>>>(q, k, v, relh, relw, aoh);
        gemm_h<2><<<dim3(CH/128, TOK/128), 256>>>(
            aoh, wprojh + (size_t)i*CH*CH, proj_b + i*CH, h, h, nullptr,
            nullptr, nullptr, TOK, CH, CH);
        layernorm_k<<<TOK, 256>>>(h, ln2_w + i*CH, ln2_b + i*CH, lnh);
        gemm_h<1><<<dim3(MLPD/128, TOK/128), 256>>>(
            lnh, wfc1h + (size_t)i*CH*MLPD, fc1_b + i*MLPD, nullptr,
            nullptr, mlph, nullptr, nullptr, TOK, MLPD, CH);
        float* dst = (i == 3) ? (float*)d_out : h;
        gemm_h<2><<<dim3(CH/128, TOK/128), 256>>>(
            mlph, wfc2h + (size_t)i*MLPD*CH, fc2_b + i*CH, h, dst, nullptr,
            nullptr, nullptr, TOK, CH, MLPD);
    }
}

// round 12
// speedup vs baseline: 3.3304x; 1.0967x over previous
#include <cuda_runtime.h>
#include <cuda_fp16.h>
#include <math.h>
#include <stdint.h>

#define TOK  4096
#define CH   768
#define NSEQ 1024
#define BHD  48
#define HD   64
#define MLPD 3072
#define QKVD 2304

// ---------------- scratch (device globals; no allocations) ----------------
__device__ float  g_h   [TOK*CH];
__device__ __half g_lnh [TOK*CH];
__device__ __half g_colh[TOK*CH];
__device__ __half g_wth [CH*CH];
__device__ __half g_qh  [BHD*NSEQ*HD];   // [bh][key][d], pre-scaled by 0.125
__device__ __half g_kh  [BHD*NSEQ*HD];   // [bh][key][d]
__device__ __half g_vh  [BHD*HD*NSEQ];   // [bh][d][key]  (transposed!)
__device__ float  g_relh[BHD*NSEQ*32];
__device__ float  g_relw[BHD*NSEQ*32];
__device__ __half g_aoh [TOK*CH];
__device__ __half g_mlph[TOK*MLPD];
// transposed [n][k] half weights
__device__ __half g_wqkvh[4*CH*QKVD];
__device__ __half g_wprojh[4*CH*CH];
__device__ __half g_wfc1h[4*CH*MLPD];
__device__ __half g_wfc2h[4*MLPD*CH];

// ---------------- helpers ----------------
__device__ __forceinline__ void mma_f16(float* c, const uint32_t* a, const uint32_t* b) {
    asm volatile(
        "mma.sync.aligned.m16n8k16.row.col.f32.f16.f16.f32 "
        "{%0,%1,%2,%3}, {%4,%5,%6,%7}, {%8,%9}, {%0,%1,%2,%3};\n"
        : "+f"(c[0]), "+f"(c[1]), "+f"(c[2]), "+f"(c[3])
        : "r"(a[0]), "r"(a[1]), "r"(a[2]), "r"(a[3]), "r"(b[0]), "r"(b[1]));
}

__device__ __forceinline__ void cp16(uint32_t saddr, const void* g) {
    asm volatile("cp.async.ca.shared.global [%0], [%1], 16;" :: "r"(saddr), "l"(g));
}

// ---------------- prep kernels ----------------
__global__ void wtrans_k(const float* __restrict__ w, __half* __restrict__ wt,
                         int K, int N) {
    __shared__ float t[32][33];
    size_t lo = (size_t)blockIdx.z * K * N;
    const float* wl = w + lo;
    __half* wtl = wt + lo;
    int k0 = blockIdx.x * 32, n0 = blockIdx.y * 32;
    int tx = threadIdx.x, ty = threadIdx.y;
#pragma unroll
    for (int r = 0; r < 32; r += 8)
        t[ty + r][tx] = wl[(size_t)(k0 + ty + r) * N + n0 + tx];
    __syncthreads();
#pragma unroll
    for (int r = 0; r < 32; r += 8)
        wtl[(size_t)(n0 + ty + r) * K + k0 + tx] = __float2half(t[tx][ty + r]);
}

__global__ void convhalf_k(const float* __restrict__ x, __half* __restrict__ y) {
    int idx = blockIdx.x * 256 + threadIdx.x;
    y[idx] = __float2half(x[idx]);
}

__global__ void im2col_k(const float* __restrict__ x, __half* __restrict__ out) {
    int idx = blockIdx.x * 256 + threadIdx.x;
    int token = idx / 768, kk = idx % 768;
    int ci = kk >> 8, r = kk & 255, py = r >> 4, px = r & 15;
    int b = token >> 10, g = token & 1023, gy = g >> 5, gx = g & 31;
    out[idx] = __float2half(
        x[(((size_t)(b*3 + ci) * 512) + gy*16 + py) * 512 + gx*16 + px]);
}

// rel bias from half q (pre-scaled by 0.125 -> compensate with *8)
__global__ void rel_k(const __half* __restrict__ q,
                      const float* __restrict__ rph, const float* __restrict__ rpw,
                      float* __restrict__ relh, float* __restrict__ relw) {
    int gw   = blockIdx.x * 8 + (threadIdx.x >> 5);
    int lane = threadIdx.x & 31;
    int bh = gw >> 10, qi = gw & 1023;
    int qy = qi >> 5, qx = qi & 31;
    const __half2* qp = (const __half2*)(q + ((size_t)bh * NSEQ + qi) * HD);
    const float* rh = rph + (qy - lane + 31) * HD;
    const float* rw = rpw + (qx - lane + 31) * HD;
    float sh = 0.f, sw = 0.f;
#pragma unroll
    for (int d = 0; d < 32; d++) {
        float2 qf = __half22float2(qp[d]);
        sh += qf.x * rh[2*d] + qf.y * rh[2*d+1];
        sw += qf.x * rw[2*d] + qf.y * rw[2*d+1];
    }
    relh[(size_t)gw * 32 + lane] = sh * 8.f;
    relw[(size_t)gw * 32 + lane] = sw * 8.f;
}

__global__ void layernorm_k(const float* __restrict__ x, const float* __restrict__ w,
                            const float* __restrict__ b, __half* __restrict__ y) {
    int row = blockIdx.x;
    const float* xr = x + (size_t)row * CH;
    int t = threadIdx.x;
    float v0 = xr[t], v1 = xr[t+256], v2 = xr[t+512];
    __shared__ float red[256];
    red[t] = v0 + v1 + v2;
    __syncthreads();
    for (int o = 128; o > 0; o >>= 1) { if (t < o) red[t] += red[t+o]; __syncthreads(); }
    float mean = red[0] * (1.f/768.f);
    __syncthreads();
    float d0 = v0-mean, d1 = v1-mean, d2 = v2-mean;
    red[t] = d0*d0 + d1*d1 + d2*d2;
    __syncthreads();
    for (int o = 128; o > 0; o >>= 1) { if (t < o) red[t] += red[t+o]; __syncthreads(); }
    float rstd = rsqrtf(red[0] * (1.f/768.f) + 1e-5f);
    __half* yr = y + (size_t)row * CH;
    yr[t]     = __float2half(d0 * rstd * w[t]     + b[t]);
    yr[t+256] = __float2half(d1 * rstd * w[t+256] + b[t+256]);
    yr[t+512] = __float2half(d2 * rstd * w[t+512] + b[t+512]);
}

// ---------------- fp16 cp.async double-buffered GEMM ---------------------------------
// EPI: 1 = bias+GELU -> half Ch, 2 = bias+residual -> fp32 C,
//      3 = qkv scatter -> half qh(Ch, scaled), kh, vh(transposed),
//      4 = bias + pos-embed add -> fp32 C
template <int EPI>
__global__ void __launch_bounds__(256)
gemm_h(const __half* __restrict__ A, const __half* __restrict__ Bt,
       const float* __restrict__ bias, const float* __restrict__ res,
       float* __restrict__ C, __half* __restrict__ Ch,
       __half* __restrict__ kh, __half* __restrict__ vh,
       int M, int N, int K) {
    __shared__ __half As[2][128][40];
    __shared__ __half Bs[2][128][40];

    int tx = threadIdx.x;
    int wid = tx >> 5, lane = tx & 31;
    int warpM = wid & 3, warpN = wid >> 2;
    int g = lane >> 2, tg = lane & 3;
    int brow = blockIdx.y * 128, bcol = blockIdx.x * 128;

    uint32_t sA = (uint32_t)__cvta_generic_to_shared(&As[0][0][0]);
    uint32_t sB = (uint32_t)__cvta_generic_to_shared(&Bs[0][0][0]);

    float acc[2][8][4];
#pragma unroll
    for (int i = 0; i < 2; i++)
#pragma unroll
        for (int j = 0; j < 8; j++)
#pragma unroll
            for (int l = 0; l < 4; l++) acc[i][j][l] = 0.f;

    int KT = K >> 5;

#define LOAD_STAGE(st, k0)                                                        \
    {                                                                             \
        _Pragma("unroll")                                                         \
        for (int i = 0; i < 2; i++) {                                             \
            int t4 = tx + i * 256;                                                \
            int m = t4 >> 2, c8 = t4 & 3;                                         \
            cp16(sA + ((st)*128*40 + m*40 + c8*8)*2,                              \
                 &A[(size_t)(brow + m) * K + (k0) + c8*8]);                       \
            cp16(sB + ((st)*128*40 + m*40 + c8*8)*2,                              \
                 &Bt[(size_t)(bcol + m) * K + (k0) + c8*8]);                      \
        }                                                                         \
    }

    LOAD_STAGE(0, 0);
    asm volatile("cp.async.commit_group;");

    for (int kt = 0; kt < KT; kt++) {
        if (kt + 1 < KT) {
            LOAD_STAGE((kt+1)&1, (kt+1)*32);
            asm volatile("cp.async.commit_group;");
            asm volatile("cp.async.wait_group 1;");
        } else {
            asm volatile("cp.async.wait_group 0;");
        }
        __syncthreads();

        const __half* Ast = &As[kt&1][0][0];
        const __half* Bst = &Bs[kt&1][0][0];
#pragma unroll
        for (int kk = 0; kk < 32; kk += 16) {
            uint32_t a[2][4], b[8][2];
#pragma unroll
            for (int mt = 0; mt < 2; mt++) {
                int m0 = warpM*32 + mt*16;
                a[mt][0] = *(const uint32_t*)&Ast[(m0+g  )*40 + kk + 2*tg    ];
                a[mt][1] = *(const uint32_t*)&Ast[(m0+g+8)*40 + kk + 2*tg    ];
                a[mt][2] = *(const uint32_t*)&Ast[(m0+g  )*40 + kk + 2*tg + 8];
                a[mt][3] = *(const uint32_t*)&Ast[(m0+g+8)*40 + kk + 2*tg + 8];
            }
#pragma unroll
            for (int nt = 0; nt < 8; nt++) {
                int n0 = warpN*64 + nt*8;
                b[nt][0] = *(const uint32_t*)&Bst[(n0+g)*40 + kk + 2*tg    ];
                b[nt][1] = *(const uint32_t*)&Bst[(n0+g)*40 + kk + 2*tg + 8];
            }
#pragma unroll
            for (int mt = 0; mt < 2; mt++)
#pragma unroll
                for (int nt = 0; nt < 8; nt++)
                    mma_f16(acc[mt][nt], a[mt], b[nt]);
        }
        __syncthreads();
    }
#undef LOAD_STAGE

#pragma unroll
    for (int mt = 0; mt < 2; mt++) {
#pragma unroll
        for (int nt = 0; nt < 8; nt++) {
            int r0 = brow + warpM*32 + mt*16 + g;
            int c0 = bcol + warpN*64 + nt*8 + tg*2;
#pragma unroll
            for (int e = 0; e < 4; e++) {
                int row = r0 + (e >> 1) * 8;
                int col = c0 + (e & 1);
                float v = acc[mt][nt][e] + bias[col];
                if (EPI == 1) {
                    v = 0.5f * v * (1.f + erff(v * 0.70710678118f));
                    Ch[(size_t)row * N + col] = __float2half(v);
                } else if (EPI == 2) {
                    C[(size_t)row * N + col] = v + res[(size_t)row * N + col];
                } else if (EPI == 3) {
                    int which = col / 768, rem = col - which * 768;
                    int head = rem >> 6, d = rem & 63;
                    int b_ = row >> 10, n_ = row & 1023;
                    if (which == 0)
                        Ch[((size_t)(b_*12 + head) * NSEQ + n_) * HD + d] =
                            __float2half(v * 0.125f);
                    else if (which == 1)
                        kh[((size_t)(b_*12 + head) * NSEQ + n_) * HD + d] =
                            __float2half(v);
                    else
                        vh[((size_t)(b_*12 + head) * HD + d) * NSEQ + n_] =
                            __float2half(v);
                } else if (EPI == 4) {
                    C[(size_t)row * N + col] = v + res[(size_t)(row & 1023) * CH + col];
                } else {
                    C[(size_t)row * N + col] = v;
                }
            }
        }
    }
}

// ---------------- fp16 fused flash attention -----------------------------------------
// float region: RH 0, RW 4224, Ms 8448, Ls 8576, Al 8704, Pmax 8832, Psum 9088 (end 9344)
// half  region: Qs 0 [128][72], Ks 9216 [128][72], Vs 18432 [64][136], Ps 27136 [128][136]
#define FA_FLOATS 9344
#define FA_HALVES 44544
#define FA_SMEM_BYTES (FA_FLOATS*4 + FA_HALVES*2)

__global__ void __launch_bounds__(256)
flash_attn(const __half* __restrict__ qh, const __half* __restrict__ kh,
           const __half* __restrict__ vh,
           const float* __restrict__ relh, const float* __restrict__ relw,
           __half* __restrict__ out) {
    extern __shared__ float sm[];
    float* RH = sm;
    float* RW = sm + 4224;
    float* Ms = sm + 8448;
    float* Ls = sm + 8576;
    float* Al = sm + 8704;
    float* Pmax = sm + 8832;
    float* Psum = sm + 9088;
    __half* hb = (__half*)(sm + FA_FLOATS);
    __half* Qs = hb;
    __half* Ks = hb + 9216;
    __half* Vs = hb + 18432;
    __half* Ps = hb + 27136;

    int tx = threadIdx.x;
    int wid = tx >> 5, lane = tx & 31;
    int g = lane >> 2, tg = lane & 3;
    int qt = blockIdx.x, bh = blockIdx.y;
    int warpM  = wid & 3, warpN  = wid >> 2;   // S phase: 32x64 warp tiles
    int warpM2 = wid >> 1, warpN2 = wid & 1;   // O phase: 32x32 warp tiles

    const __half* Qg = qh + ((size_t)bh * NSEQ + qt * 128) * HD;
    const __half* Kg = kh + (size_t)bh * NSEQ * HD;
    const __half* Vg = vh + (size_t)bh * HD * NSEQ;

    uint32_t sQ = (uint32_t)__cvta_generic_to_shared(Qs);
    uint32_t sK = (uint32_t)__cvta_generic_to_shared(Ks);
    uint32_t sV = (uint32_t)__cvta_generic_to_shared(Vs);

    // stage Q via cp.async: 128 rows x 64 halves = 8 chunks/row -> 1024 chunks
#pragma unroll
    for (int i = 0; i < 4; i++) {
        int t4 = tx + i * 256;
        int row = t4 >> 3, c8 = t4 & 7;
        cp16(sQ + (row*72 + c8*8)*2, &Qg[row * HD + c8*8]);
    }
    asm volatile("cp.async.commit_group;");
    // stage rel tables (stride 33)
    for (int idx = tx; idx < 4096; idx += 256) {
        int row = idx >> 5, c = idx & 31;
        size_t src = ((size_t)bh * NSEQ + qt * 128 + row) * 32 + c;
        RH[row*33 + c] = relh[src];
        RW[row*33 + c] = relw[src];
    }
    if (tx < 128) { Ms[tx] = -1e30f; Ls[tx] = 0.f; }

    float o[2][4][4];
#pragma unroll
    for (int a = 0; a < 2; a++)
#pragma unroll
        for (int b = 0; b < 4; b++)
#pragma unroll
            for (int c = 0; c < 4; c++) o[a][b][c] = 0.f;

    for (int kt = 0; kt < 8; kt++) {
        __syncthreads();   // protect Ks/Vs/Ps reuse from previous iteration
        // K tile: 128 keys x 64 dims = 8 chunks/row -> 1024 chunks
#pragma unroll
        for (int i = 0; i < 4; i++) {
            int t4 = tx + i * 256;
            int row = t4 >> 3, c8 = t4 & 7;
            cp16(sK + (row*72 + c8*8)*2, &Kg[(kt*128 + row) * HD + c8*8]);
        }
        // V tile: 64 dims x 128 keys = 16 chunks/row -> 1024 chunks
#pragma unroll
        for (int i = 0; i < 4; i++) {
            int t4 = tx + i * 256;
            int d = t4 >> 4, c8 = t4 & 15;
            cp16(sV + (d*136 + c8*8)*2, &Vg[(size_t)d * NSEQ + kt*128 + c8*8]);
        }
        asm volatile("cp.async.commit_group;");
        asm volatile("cp.async.wait_group 0;");
        __syncthreads();

        // S = Qs @ Ks^T  (K = 64, 4 k16 steps)
        float s[2][8][4];
#pragma unroll
        for (int a = 0; a < 2; a++)
#pragma unroll
            for (int b = 0; b < 8; b++)
#pragma unroll
                for (int c = 0; c < 4; c++) s[a][b][c] = 0.f;
#pragma unroll
        for (int ks = 0; ks < 4; ks++) {
            int kk = ks * 16;
            uint32_t a[2][4], b[8][2];
#pragma unroll
            for (int mt = 0; mt < 2; mt++) {
                int m0 = warpM*32 + mt*16;
                a[mt][0] = *(const uint32_t*)&Qs[(m0+g  )*72 + kk + 2*tg    ];
                a[mt][1] = *(const uint32_t*)&Qs[(m0+g+8)*72 + kk + 2*tg    ];
                a[mt][2] = *(const uint32_t*)&Qs[(m0+g  )*72 + kk + 2*tg + 8];
                a[mt][3] = *(const uint32_t*)&Qs[(m0+g+8)*72 + kk + 2*tg + 8];
            }
#pragma unroll
            for (int nt = 0; nt < 8; nt++) {
                int n0 = warpN*64 + nt*8;
                b[nt][0] = *(const uint32_t*)&Ks[(n0+g)*72 + kk + 2*tg    ];
                b[nt][1] = *(const uint32_t*)&Ks[(n0+g)*72 + kk + 2*tg + 8];
            }
#pragma unroll
            for (int mt = 0; mt < 2; mt++)
#pragma unroll
                for (int nt = 0; nt < 8; nt++)
                    mma_f16(s[mt][nt], a[mt], b[nt]);
        }

        // + rel bias; row-wise running max
        float rmax[2][2];
#pragma unroll
        for (int mt = 0; mt < 2; mt++)
#pragma unroll
            for (int rr = 0; rr < 2; rr++) {
                int row = warpM*32 + mt*16 + rr*8 + g;
                float rh0 = RH[row*33 + kt*4 + warpN*2];
                float rh1 = RH[row*33 + kt*4 + warpN*2 + 1];
                float mx = -1e30f;
#pragma unroll
                for (int nt = 0; nt < 8; nt++) {
#pragma unroll
                    for (int e1 = 0; e1 < 2; e1++) {
                        float rw = RW[row*33 + 8*(nt & 3) + 2*tg + e1];
                        float vv = s[mt][nt][rr*2 + e1] + ((nt < 4) ? rh0 : rh1) + rw;
                        s[mt][nt][rr*2 + e1] = vv;
                        mx = fmaxf(mx, vv);
                    }
                }
                rmax[mt][rr] = mx;
            }
#pragma unroll
        for (int mt = 0; mt < 2; mt++)
#pragma unroll
            for (int rr = 0; rr < 2; rr++) {
                float v = rmax[mt][rr];
                v = fmaxf(v, __shfl_xor_sync(0xffffffffu, v, 1));
                v = fmaxf(v, __shfl_xor_sync(0xffffffffu, v, 2));
                if (tg == 0) Pmax[warpN*128 + warpM*32 + mt*16 + rr*8 + g] = v;
            }
        __syncthreads();
        if (tx < 128) {
            float m_old = Ms[tx];
            float m_new = fmaxf(m_old, fmaxf(Pmax[tx], Pmax[128 + tx]));
            float al = __expf(m_old - m_new);
            Al[tx] = al;
            Ls[tx] *= al;
            Ms[tx] = m_new;
        }
        __syncthreads();

        // exp, partial sums, write P [m][key] half
        float rsum[2][2];
#pragma unroll
        for (int mt = 0; mt < 2; mt++)
#pragma unroll
            for (int rr = 0; rr < 2; rr++) {
                int rowl = warpM*32 + mt*16 + rr*8 + g;
                float mrow = Ms[rowl];
                float sum = 0.f;
#pragma unroll
                for (int nt = 0; nt < 8; nt++) {
                    float p0 = __expf(s[mt][nt][rr*2 + 0] - mrow);
                    float p1 = __expf(s[mt][nt][rr*2 + 1] - mrow);
                    sum += p0 + p1;
                    int col = warpN*64 + nt*8 + tg*2;
                    *(half2*)&Ps[rowl*136 + col] = __floats2half2_rn(p0, p1);
                }
                rsum[mt][rr] = sum;
            }
#pragma unroll
        for (int mt = 0; mt < 2; mt++)
#pragma unroll
            for (int rr = 0; rr < 2; rr++) {
                float v = rsum[mt][rr];
                v += __shfl_xor_sync(0xffffffffu, v, 1);
                v += __shfl_xor_sync(0xffffffffu, v, 2);
                if (tg == 0) Psum[warpN*128 + warpM*32 + mt*16 + rr*8 + g] = v;
            }
        __syncthreads();
        if (tx < 128) Ls[tx] += Psum[tx] + Psum[128 + tx];

        // rescale O, then O += P @ V  (K = 128, 8 k16 steps)
        float alv[2][2];
#pragma unroll
        for (int mt = 0; mt < 2; mt++)
#pragma unroll
            for (int rr = 0; rr < 2; rr++)
                alv[mt][rr] = Al[warpM2*32 + mt*16 + rr*8 + g];
#pragma unroll
        for (int mt = 0; mt < 2; mt++)
#pragma unroll
            for (int nt = 0; nt < 4; nt++)
#pragma unroll
                for (int e = 0; e < 4; e++)
                    o[mt][nt][e] *= alv[mt][e >> 1];
#pragma unroll
        for (int ks = 0; ks < 8; ks++) {
            int kk = ks * 16;
            uint32_t a[2][4], b[4][2];
#pragma unroll
            for (int mt = 0; mt < 2; mt++) {
                int m0 = warpM2*32 + mt*16;
                a[mt][0] = *(const uint32_t*)&Ps[(m0+g  )*136 + kk + 2*tg    ];
                a[mt][1] = *(const uint32_t*)&Ps[(m0+g+8)*136 + kk + 2*tg    ];
                a[mt][2] = *(const uint32_t*)&Ps[(m0+g  )*136 + kk + 2*tg + 8];
                a[mt][3] = *(const uint32_t*)&Ps[(m0+g+8)*136 + kk + 2*tg + 8];
            }
#pragma unroll
            for (int nt = 0; nt < 4; nt++) {
                int n0 = warpN2*32 + nt*8;
                b[nt][0] = *(const uint32_t*)&Vs[(n0+g)*136 + kk + 2*tg    ];
                b[nt][1] = *(const uint32_t*)&Vs[(n0+g)*136 + kk + 2*tg + 8];
            }
#pragma unroll
            for (int mt = 0; mt < 2; mt++)
#pragma unroll
                for (int nt = 0; nt < 4; nt++)
                    mma_f16(o[mt][nt], a[mt], b[nt]);
        }
    }
    __syncthreads();

    int b_ = bh / 12, head = bh % 12;
    float linv[2][2];
#pragma unroll
    for (int mt = 0; mt < 2; mt++)
#pragma unroll
        for (int rr = 0; rr < 2; rr++)
            linv[mt][rr] = 1.f / Ls[warpM2*32 + mt*16 + rr*8 + g];
#pragma unroll
    for (int mt = 0; mt < 2; mt++) {
#pragma unroll
        for (int nt = 0; nt < 4; nt++) {
#pragma unroll
            for (int e = 0; e < 4; e++) {
                int r = warpM2*32 + mt*16 + (e >> 1)*8 + g;
                int c = warpN2*32 + nt*8 + tg*2 + (e & 1);
                out[((size_t)(b_ * NSEQ + qt*128 + r)) * CH + head*64 + c] =
                    __float2half(o[mt][nt][e] * linv[mt][e >> 1]);
            }
        }
    }
}

// ---------------- orchestration ----------------
extern "C" void kernel_launch(void* const* d_in, const int* in_sizes, int n_in,
                              void* d_out, int out_size) {
    const float* x         = (const float*)d_in[0];
    const float* conv_w    = (const float*)d_in[1];
    const float* conv_b    = (const float*)d_in[2];
    const float* pos_embed = (const float*)d_in[3];
    const float* ln1_w     = (const float*)d_in[4];
    const float* ln1_b     = (const float*)d_in[5];
    const float* qkv_w     = (const float*)d_in[6];
    const float* qkv_b     = (const float*)d_in[7];
    const float* proj_w    = (const float*)d_in[8];
    const float* proj_b    = (const float*)d_in[9];
    const float* rel_pos_h = (const float*)d_in[10];
    const float* rel_pos_w = (const float*)d_in[11];
    const float* ln2_w     = (const float*)d_in[12];
    const float* ln2_b     = (const float*)d_in[13];
    const float* fc1_w     = (const float*)d_in[14];
    const float* fc1_b     = (const float*)d_in[15];
    const float* fc2_w     = (const float*)d_in[16];
    const float* fc2_b     = (const float*)d_in[17];

    float *h, *relh, *relw;
    __half *lnh, *colh, *wth, *qh, *kh, *vh, *aoh, *mlph;
    __half *wqkvh, *wprojh, *wfc1h, *wfc2h;
    cudaGetSymbolAddress((void**)&h,     g_h);
    cudaGetSymbolAddress((void**)&lnh,   g_lnh);
    cudaGetSymbolAddress((void**)&colh,  g_colh);
    cudaGetSymbolAddress((void**)&wth,   g_wth);
    cudaGetSymbolAddress((void**)&qh,    g_qh);
    cudaGetSymbolAddress((void**)&kh,    g_kh);
    cudaGetSymbolAddress((void**)&vh,    g_vh);
    cudaGetSymbolAddress((void**)&relh,  g_relh);
    cudaGetSymbolAddress((void**)&relw,  g_relw);
    cudaGetSymbolAddress((void**)&aoh,   g_aoh);
    cudaGetSymbolAddress((void**)&mlph,  g_mlph);
    cudaGetSymbolAddress((void**)&wqkvh, g_wqkvh);
    cudaGetSymbolAddress((void**)&wprojh,g_wprojh);
    cudaGetSymbolAddress((void**)&wfc1h, g_wfc1h);
    cudaGetSymbolAddress((void**)&wfc2h, g_wfc2h);

    static bool attr_set = false;
    if (!attr_set) {
        cudaFuncSetAttribute(flash_attn, cudaFuncAttributeMaxDynamicSharedMemorySize,
                             FA_SMEM_BYTES);
        attr_set = true;
    }

    dim3 tb(32, 8);
    wtrans_k<<<dim3(CH/32,  QKVD/32, 4), tb>>>(qkv_w,  wqkvh, CH,   QKVD);
    wtrans_k<<<dim3(CH/32,  CH/32,   4), tb>>>(proj_w, wprojh, CH,  CH);
    wtrans_k<<<dim3(CH/32,  MLPD/32, 4), tb>>>(fc1_w,  wfc1h, CH,   MLPD);
    wtrans_k<<<dim3(MLPD/32,CH/32,   4), tb>>>(fc2_w,  wfc2h, MLPD, CH);
    convhalf_k<<<CH*CH/256, 256>>>(conv_w, wth);

    im2col_k<<<TOK*CH/256, 256>>>(x, colh);
    gemm_h<4><<<dim3(CH/128, TOK/128), 256>>>(
        colh, wth, conv_b, pos_embed, h, nullptr, nullptr, nullptr, TOK, CH, CH);

    for (int i = 0; i < 4; i++) {
        layernorm_k<<<TOK, 256>>>(h, ln1_w + i*CH, ln1_b + i*CH, lnh);
        gemm_h<3><<<dim3(QKVD/128, TOK/128), 256>>>(
            lnh, wqkvh + (size_t)i*CH*QKVD, qkv_b + i*QKVD, nullptr,
            nullptr, qh, kh, vh, TOK, QKVD, CH);
        rel_k<<<BHD*NSEQ/8, 256>>>(qh, rel_pos_h + i*63*HD, rel_pos_w + i*63*HD,
                                   relh, relw);
        flash_attn<<<dim3(8, BHD), 256, FA_SMEM_BYTES>>>(qh, kh, vh, relh, relw, aoh);
        gemm_h<2><<<dim3(CH/128, TOK/128), 256>>>(
            aoh, wprojh + (size_t)i*CH*CH, proj_b + i*CH, h, h, nullptr,
            nullptr, nullptr, TOK, CH, CH);
        layernorm_k<<<TOK, 256>>>(h, ln2_w + i*CH, ln2_b + i*CH, lnh);
        gemm_h<1><<<dim3(MLPD/128, TOK/128), 256>>>(
            lnh, wfc1h + (size_t)i*CH*MLPD, fc1_b + i*MLPD, nullptr,
            nullptr, mlph, nullptr, nullptr, TOK, MLPD, CH);
        float* dst = (i == 3) ? (float*)d_out : h;
        gemm_h<2><<<dim3(CH/128, TOK/128), 256>>>(
            mlph, wfc2h + (size_t)i*MLPD*CH, fc2_b + i*CH, h, dst, nullptr,
            nullptr, nullptr, TOK, CH, MLPD);
    }
}